// round 1
// baseline (speedup 1.0000x reference)
#include <cuda_runtime.h>
#include <math.h>

// ---------------- problem constants ----------------
#define D_MODEL 1024
#define D_FF    4096
#define NH      16
#define DH      64
#define TOT     1024          // NH*DH
#define BATCH   2
#define SEQ     2048
#define NTOK    (BATCH*SEQ)   // 4096

// ---------------- scratch (device globals: allocation-free) ----------------
__device__ float g_h   [(size_t)NTOK * D_MODEL];          // 16 MB
__device__ float g_qkv [(size_t)NTOK * 3 * TOT];          // 48 MB
__device__ float g_S   [(size_t)BATCH * NH * SEQ * SEQ];  // 512 MB
__device__ float g_attn[(size_t)NTOK * TOT];              // 16 MB
__device__ float g_x2  [(size_t)NTOK * D_MODEL];          // 16 MB
__device__ float g_gate[(size_t)NTOK * D_FF];             // 64 MB
__device__ float g_up  [(size_t)NTOK * D_FF];             // 64 MB

// ---------------- block reductions (256 threads) ----------------
__device__ __forceinline__ float block_reduce_sum(float v) {
    __shared__ float sh[33];
    int lane = threadIdx.x & 31, wid = threadIdx.x >> 5;
    #pragma unroll
    for (int o = 16; o; o >>= 1) v += __shfl_xor_sync(0xffffffffu, v, o);
    if (lane == 0) sh[wid] = v;
    __syncthreads();
    if (wid == 0) {
        v = (lane < (blockDim.x >> 5)) ? sh[lane] : 0.f;
        #pragma unroll
        for (int o = 16; o; o >>= 1) v += __shfl_xor_sync(0xffffffffu, v, o);
        if (lane == 0) sh[32] = v;
    }
    __syncthreads();
    float r = sh[32];
    __syncthreads();
    return r;
}

__device__ __forceinline__ float block_reduce_max(float v) {
    __shared__ float sh[33];
    int lane = threadIdx.x & 31, wid = threadIdx.x >> 5;
    #pragma unroll
    for (int o = 16; o; o >>= 1) v = fmaxf(v, __shfl_xor_sync(0xffffffffu, v, o));
    if (lane == 0) sh[wid] = v;
    __syncthreads();
    if (wid == 0) {
        v = (lane < (blockDim.x >> 5)) ? sh[lane] : -1e30f;
        #pragma unroll
        for (int o = 16; o; o >>= 1) v = fmaxf(v, __shfl_xor_sync(0xffffffffu, v, o));
        if (lane == 0) sh[32] = v;
    }
    __syncthreads();
    float r = sh[32];
    __syncthreads();
    return r;
}

// ---------------- RMSNorm: one block per token ----------------
__global__ void rmsnorm_kernel(const float* __restrict__ x,
                               const float* __restrict__ w,
                               float* __restrict__ o) {
    const size_t base = (size_t)blockIdx.x * D_MODEL;
    float ss = 0.f;
    for (int i = threadIdx.x; i < D_MODEL; i += 256) {
        float v = x[base + i];
        ss += v * v;
    }
    ss = block_reduce_sum(ss);
    float r = rsqrtf(ss * (1.0f / D_MODEL) + 1e-6f);
    for (int i = threadIdx.x; i < D_MODEL; i += 256)
        o[base + i] = x[base + i] * r * w[i];
}

// ---------------- RoPE in-place on q,k parts of qkv ----------------
// grid = NTOK tokens, 512 threads = 16 heads * 32 pairs
__global__ void rope_kernel(float* __restrict__ qkv) {
    const int t   = blockIdx.x;          // global token
    const int pos = t & (SEQ - 1);       // position within sequence
    const int h   = threadIdx.x >> 5;
    const int i   = threadIdx.x & 31;
    // inv_freq = 10000^(-2i/64)
    float invf = expf(-(2.0f * (float)i / (float)DH) * logf(10000.0f));
    float fr = (float)pos * invf;
    float s, c;
    sincosf(fr, &s, &c);
    float* q = qkv + (size_t)t * (3 * TOT) + h * DH;
    float q1 = q[i], q2 = q[i + 32];
    q[i]      = q1 * c - q2 * s;
    q[i + 32] = q2 * c + q1 * s;
    float* k = q + TOT;
    float k1 = k[i], k2 = k[i + 32];
    k[i]      = k1 * c - k2 * s;
    k[i + 32] = k2 * c + k1 * s;
}

// ---------------- causal row softmax, in-place on S ----------------
// grid = (SEQ, B*H), 256 threads; row length SEQ held in 8 regs/thread
__global__ void softmax_causal_kernel(float* __restrict__ S) {
    const int i  = blockIdx.x;
    const int bh = blockIdx.y;
    float* row = S + ((size_t)bh * SEQ + i) * SEQ;
    const int L = i + 1;
    float v[8];
    float m = -1e30f;
    #pragma unroll
    for (int r = 0; r < 8; r++) {
        int j = threadIdx.x + r * 256;
        v[r] = (j < L) ? row[j] : -1e30f;
        m = fmaxf(m, v[r]);
    }
    m = block_reduce_max(m);
    float s = 0.f;
    #pragma unroll
    for (int r = 0; r < 8; r++) {
        int j = threadIdx.x + r * 256;
        v[r] = (j < L) ? expf(v[r] - m) : 0.f;
        s += v[r];
    }
    s = block_reduce_sum(s);
    float inv = 1.f / s;
    #pragma unroll
    for (int r = 0; r < 8; r++) {
        int j = threadIdx.x + r * 256;
        row[j] = v[r] * inv;   // zeros beyond causal limit -> PV can run full-K
    }
}

// ---------------- SwiGLU elementwise: g = silu(g) * u ----------------
__global__ void swiglu_kernel(float* __restrict__ g, const float* __restrict__ u, int n4) {
    int idx = blockIdx.x * blockDim.x + threadIdx.x;
    int stride = gridDim.x * blockDim.x;
    for (; idx < n4; idx += stride) {
        float4 gv = ((float4*)g)[idx];
        float4 uv = ((const float4*)u)[idx];
        gv.x = gv.x / (1.f + expf(-gv.x)) * uv.x;
        gv.y = gv.y / (1.f + expf(-gv.y)) * uv.y;
        gv.z = gv.z / (1.f + expf(-gv.z)) * uv.z;
        gv.w = gv.w / (1.f + expf(-gv.w)) * uv.w;
        ((float4*)g)[idx] = gv;
    }
}

// ---------------- register-tiled SGEMM ----------------
// C[M,N] = alpha * A[M,K] @ op(B)  (+ Res)
//   B_KN=false: B is [N,K] row-major (weights, "NT")
//   B_KN=true : B is [K,N] row-major (PV, "NN")
// Batched over grid.z with z decomposed as (z>>4, z&15) and separate strides,
// so attention can address per-(batch, head) slices of interleaved qkv.
template<int BM, int BN, int BK, int TM, int TN, bool B_KN, bool ADD_RES, bool CAUSAL>
__global__ void __launch_bounds__((BM / TM) * (BN / TN))
sgemm_kernel(const float* __restrict__ A, int lda,
             const float* __restrict__ B, int ldb,
             float* __restrict__ C, int ldc,
             const float* __restrict__ Res,
             int M, int N, int K, float alpha,
             long long sAb, long long sAh,
             long long sBb, long long sBh,
             long long sCb, long long sCh) {
    constexpr int THREADS = (BM / TM) * (BN / TN);
    const int bx = blockIdx.x, by = blockIdx.y;
    if (CAUSAL && (long long)bx * BN > (long long)by * BM + (BM - 1)) return;

    const int zb = blockIdx.z >> 4, zh = blockIdx.z & 15;
    A += zb * sAb + zh * sAh;
    B += zb * sBb + zh * sBh;
    C += zb * sCb + zh * sCh;
    if (ADD_RES) Res += zb * sCb + zh * sCh;

    __shared__ float As[BK][BM + 4];
    __shared__ float Bs[BK][BN + 4];

    const int tid = threadIdx.x;
    const int tx  = tid % (BN / TN);
    const int ty  = tid / (BN / TN);
    const int m0  = by * BM, n0 = bx * BN;

    float acc[TM][TN];
    #pragma unroll
    for (int i = 0; i < TM; i++)
        #pragma unroll
        for (int j = 0; j < TN; j++) acc[i][j] = 0.f;

    for (int kt = 0; kt < K; kt += BK) {
        // A tile: [BM][BK] -> As[k][m] (transposed)
        for (int idx = tid; idx < BM * (BK / 4); idx += THREADS) {
            int m = idx / (BK / 4), kv = idx % (BK / 4);
            float4 v = *(const float4*)(A + (size_t)(m0 + m) * lda + kt + kv * 4);
            As[kv * 4 + 0][m] = v.x;
            As[kv * 4 + 1][m] = v.y;
            As[kv * 4 + 2][m] = v.z;
            As[kv * 4 + 3][m] = v.w;
        }
        if (!B_KN) {
            // B tile: [BN][BK] -> Bs[k][n] (transposed)
            for (int idx = tid; idx < BN * (BK / 4); idx += THREADS) {
                int n = idx / (BK / 4), kv = idx % (BK / 4);
                float4 v = *(const float4*)(B + (size_t)(n0 + n) * ldb + kt + kv * 4);
                Bs[kv * 4 + 0][n] = v.x;
                Bs[kv * 4 + 1][n] = v.y;
                Bs[kv * 4 + 2][n] = v.z;
                Bs[kv * 4 + 3][n] = v.w;
            }
        } else {
            // B tile: [BK][BN] -> Bs[k][n] (direct, fully coalesced)
            for (int idx = tid; idx < BK * (BN / 4); idx += THREADS) {
                int k = idx / (BN / 4), nv = idx % (BN / 4);
                *(float4*)&Bs[k][nv * 4] =
                    *(const float4*)(B + (size_t)(kt + k) * ldb + n0 + nv * 4);
            }
        }
        __syncthreads();

        #pragma unroll
        for (int kk = 0; kk < BK; kk++) {
            float a[TM], b[TN];
            #pragma unroll
            for (int i = 0; i < TM; i += 4)
                *(float4*)&a[i] = *(const float4*)&As[kk][ty * TM + i];
            #pragma unroll
            for (int j = 0; j < TN; j += 4)
                *(float4*)&b[j] = *(const float4*)&Bs[kk][tx * TN + j];
            #pragma unroll
            for (int i = 0; i < TM; i++)
                #pragma unroll
                for (int j = 0; j < TN; j++)
                    acc[i][j] = fmaf(a[i], b[j], acc[i][j]);
        }
        __syncthreads();
    }

    // epilogue
    #pragma unroll
    for (int i = 0; i < TM; i++) {
        int m = m0 + ty * TM + i;
        #pragma unroll
        for (int j = 0; j < TN; j += 4) {
            int n = n0 + tx * TN + j;
            float4 v;
            v.x = acc[i][j + 0] * alpha;
            v.y = acc[i][j + 1] * alpha;
            v.z = acc[i][j + 2] * alpha;
            v.w = acc[i][j + 3] * alpha;
            if (ADD_RES) {
                float4 r = *(const float4*)(Res + (size_t)m * ldc + n);
                v.x += r.x; v.y += r.y; v.z += r.z; v.w += r.w;
            }
            *(float4*)(C + (size_t)m * ldc + n) = v;
        }
    }
}

// ---------------- launch ----------------
extern "C" void kernel_launch(void* const* d_in, const int* in_sizes, int n_in,
                              void* d_out, int out_size) {
    const float* x      = (const float*)d_in[0];
    const float* w_ln1  = (const float*)d_in[1];
    const float* w_qkv  = (const float*)d_in[2];
    const float* w_out  = (const float*)d_in[3];
    const float* w_ln2  = (const float*)d_in[4];
    const float* w_gate = (const float*)d_in[5];
    const float* w_up   = (const float*)d_in[6];
    const float* w_down = (const float*)d_in[7];
    float* out = (float*)d_out;

    void* p;
    cudaGetSymbolAddress(&p, g_h);    float* h    = (float*)p;
    cudaGetSymbolAddress(&p, g_qkv);  float* qkv  = (float*)p;
    cudaGetSymbolAddress(&p, g_S);    float* S    = (float*)p;
    cudaGetSymbolAddress(&p, g_attn); float* attn = (float*)p;
    cudaGetSymbolAddress(&p, g_x2);   float* x2   = (float*)p;
    cudaGetSymbolAddress(&p, g_gate); float* gate = (float*)p;
    cudaGetSymbolAddress(&p, g_up);   float* up   = (float*)p;

    const long long z0 = 0;

    // 1) h = rmsnorm(x, w_ln1)
    rmsnorm_kernel<<<NTOK, 256>>>(x, w_ln1, h);

    // 2) qkv = h @ w_qkv^T   [4096 x 3072], K=1024
    sgemm_kernel<128,128,16,8,8,false,false,false>
        <<<dim3(3*TOT/128, NTOK/128, 1), 256>>>(
        h, D_MODEL, w_qkv, D_MODEL, qkv, 3*TOT, nullptr,
        NTOK, 3*TOT, D_MODEL, 1.f, z0, z0, z0, z0, z0, z0);

    // 3) RoPE on q,k
    rope_kernel<<<NTOK, 512>>>(qkv);

    // 4) S = scale * Q @ K^T per (b,h); skip blocks above the diagonal
    sgemm_kernel<128,128,16,8,8,false,false,true>
        <<<dim3(SEQ/128, SEQ/128, BATCH*NH), 256>>>(
        qkv, 3*TOT, qkv + TOT, 3*TOT, S, SEQ, nullptr,
        SEQ, SEQ, DH, 0.125f,
        (long long)SEQ*3*TOT, DH,            // A (Q): batch, head strides
        (long long)SEQ*3*TOT, DH,            // B (K)
        (long long)NH*SEQ*SEQ, (long long)SEQ*SEQ); // C (S)

    // 5) causal softmax in place (writes zeros above diagonal)
    softmax_causal_kernel<<<dim3(SEQ, BATCH*NH), 256>>>(S);

    // 6) attn = P @ V  (NN form: V is [K=2048 tokens][N=64 dims] with ld 3072)
    sgemm_kernel<128,64,16,8,4,true,false,false>
        <<<dim3(1, SEQ/128, BATCH*NH), 256>>>(
        S, SEQ, qkv + 2*TOT, 3*TOT, attn, TOT, nullptr,
        SEQ, DH, SEQ, 1.f,
        (long long)NH*SEQ*SEQ, (long long)SEQ*SEQ,   // A (P)
        (long long)SEQ*3*TOT, DH,                    // B (V)
        (long long)SEQ*TOT, DH);                     // C (attn, [t][h*64+d])

    // 7) x2 = x + attn @ w_out^T
    sgemm_kernel<128,128,16,8,8,false,true,false>
        <<<dim3(D_MODEL/128, NTOK/128, 1), 256>>>(
        attn, TOT, w_out, TOT, x2, D_MODEL, x,
        NTOK, D_MODEL, TOT, 1.f, z0, z0, z0, z0, z0, z0);

    // 8) h = rmsnorm(x2, w_ln2)
    rmsnorm_kernel<<<NTOK, 256>>>(x2, w_ln2, h);

    // 9) gate = h @ w_gate^T ; up = h @ w_up^T   [4096 x 4096], K=1024
    sgemm_kernel<128,128,16,8,8,false,false,false>
        <<<dim3(D_FF/128, NTOK/128, 1), 256>>>(
        h, D_MODEL, w_gate, D_MODEL, gate, D_FF, nullptr,
        NTOK, D_FF, D_MODEL, 1.f, z0, z0, z0, z0, z0, z0);
    sgemm_kernel<128,128,16,8,8,false,false,false>
        <<<dim3(D_FF/128, NTOK/128, 1), 256>>>(
        h, D_MODEL, w_up, D_MODEL, up, D_FF, nullptr,
        NTOK, D_FF, D_MODEL, 1.f, z0, z0, z0, z0, z0, z0);

    // 10) gate = silu(gate) * up
    swiglu_kernel<<<4096, 256>>>(gate, up, NTOK * D_FF / 4);

    // 11) out = x2 + gate @ w_down^T   [4096 x 1024], K=4096
    sgemm_kernel<128,128,16,8,8,false,true,false>
        <<<dim3(D_MODEL/128, NTOK/128, 1), 256>>>(
        gate, D_FF, w_down, D_FF, out, D_MODEL, x2,
        NTOK, D_MODEL, D_FF, 1.f, z0, z0, z0, z0, z0, z0);
}

// round 2
// speedup vs baseline: 3.1632x; 3.1632x over previous
#include <cuda_runtime.h>
#include <math.h>
#include <stdint.h>

// ---------------- problem constants ----------------
#define D_MODEL 1024
#define D_FF    4096
#define NH      16
#define DH      64
#define TOT     1024          // NH*DH
#define BATCH   2
#define SEQ     2048
#define NTOK    (BATCH*SEQ)   // 4096

// ---------------- scratch (device globals: allocation-free) ----------------
__device__ float g_h   [(size_t)NTOK * D_MODEL];
__device__ float g_qkv [(size_t)NTOK * 3 * TOT];
__device__ float g_S   [(size_t)BATCH * NH * SEQ * SEQ];
__device__ float g_attn[(size_t)NTOK * TOT];
__device__ float g_x2  [(size_t)NTOK * D_MODEL];
__device__ float g_gate[(size_t)NTOK * D_FF];
__device__ float g_up  [(size_t)NTOK * D_FF];

// ---------------- small helpers ----------------
__device__ __forceinline__ void cp16(uint32_t dst, const void* src) {
    asm volatile("cp.async.cg.shared.global [%0], [%1], 16;" :: "r"(dst), "l"(src));
}
__device__ __forceinline__ uint32_t f2tf32(float f) {
    uint32_t r;
    asm("cvt.rna.tf32.f32 %0, %1;" : "=r"(r) : "f"(f));
    return r;
}
__device__ __forceinline__ void mma_tf32(float& c0, float& c1, float& c2, float& c3,
                                         uint32_t a0, uint32_t a1, uint32_t a2, uint32_t a3,
                                         uint32_t b0, uint32_t b1) {
    asm volatile(
        "mma.sync.aligned.m16n8k8.row.col.f32.tf32.tf32.f32 "
        "{%0,%1,%2,%3}, {%4,%5,%6,%7}, {%8,%9}, {%0,%1,%2,%3};"
        : "+f"(c0), "+f"(c1), "+f"(c2), "+f"(c3)
        : "r"(a0), "r"(a1), "r"(a2), "r"(a3), "r"(b0), "r"(b1));
}

// ---------------- block reductions (256 threads) ----------------
__device__ __forceinline__ float block_reduce_sum(float v) {
    __shared__ float sh[33];
    int lane = threadIdx.x & 31, wid = threadIdx.x >> 5;
    #pragma unroll
    for (int o = 16; o; o >>= 1) v += __shfl_xor_sync(0xffffffffu, v, o);
    if (lane == 0) sh[wid] = v;
    __syncthreads();
    if (wid == 0) {
        v = (lane < (blockDim.x >> 5)) ? sh[lane] : 0.f;
        #pragma unroll
        for (int o = 16; o; o >>= 1) v += __shfl_xor_sync(0xffffffffu, v, o);
        if (lane == 0) sh[32] = v;
    }
    __syncthreads();
    float r = sh[32];
    __syncthreads();
    return r;
}

__device__ __forceinline__ float block_reduce_max(float v) {
    __shared__ float sh[33];
    int lane = threadIdx.x & 31, wid = threadIdx.x >> 5;
    #pragma unroll
    for (int o = 16; o; o >>= 1) v = fmaxf(v, __shfl_xor_sync(0xffffffffu, v, o));
    if (lane == 0) sh[wid] = v;
    __syncthreads();
    if (wid == 0) {
        v = (lane < (blockDim.x >> 5)) ? sh[lane] : -1e30f;
        #pragma unroll
        for (int o = 16; o; o >>= 1) v = fmaxf(v, __shfl_xor_sync(0xffffffffu, v, o));
        if (lane == 0) sh[32] = v;
    }
    __syncthreads();
    float r = sh[32];
    __syncthreads();
    return r;
}

// ---------------- RMSNorm ----------------
__global__ void rmsnorm_kernel(const float* __restrict__ x,
                               const float* __restrict__ w,
                               float* __restrict__ o) {
    const size_t base = (size_t)blockIdx.x * D_MODEL;
    float ss = 0.f;
    for (int i = threadIdx.x; i < D_MODEL; i += 256) {
        float v = x[base + i];
        ss += v * v;
    }
    ss = block_reduce_sum(ss);
    float r = rsqrtf(ss * (1.0f / D_MODEL) + 1e-6f);
    for (int i = threadIdx.x; i < D_MODEL; i += 256)
        o[base + i] = x[base + i] * r * w[i];
}

// ---------------- RoPE in-place on q,k parts of qkv ----------------
__global__ void rope_kernel(float* __restrict__ qkv) {
    const int t   = blockIdx.x;
    const int pos = t & (SEQ - 1);
    const int h   = threadIdx.x >> 5;
    const int i   = threadIdx.x & 31;
    float invf = expf(-(2.0f * (float)i / (float)DH) * logf(10000.0f));
    float fr = (float)pos * invf;
    float s, c;
    sincosf(fr, &s, &c);
    float* q = qkv + (size_t)t * (3 * TOT) + h * DH;
    float q1 = q[i], q2 = q[i + 32];
    q[i]      = q1 * c - q2 * s;
    q[i + 32] = q2 * c + q1 * s;
    float* k = q + TOT;
    float k1 = k[i], k2 = k[i + 32];
    k[i]      = k1 * c - k2 * s;
    k[i + 32] = k2 * c + k1 * s;
}

// ---------------- causal row softmax ----------------
__global__ void softmax_causal_kernel(float* __restrict__ S) {
    const int i  = blockIdx.x;
    const int bh = blockIdx.y;
    float* row = S + ((size_t)bh * SEQ + i) * SEQ;
    const int L = i + 1;
    float v[8];
    float m = -1e30f;
    #pragma unroll
    for (int r = 0; r < 8; r++) {
        int j = threadIdx.x + r * 256;
        v[r] = (j < L) ? row[j] : -1e30f;
        m = fmaxf(m, v[r]);
    }
    m = block_reduce_max(m);
    float s = 0.f;
    #pragma unroll
    for (int r = 0; r < 8; r++) {
        int j = threadIdx.x + r * 256;
        v[r] = (j < L) ? expf(v[r] - m) : 0.f;
        s += v[r];
    }
    s = block_reduce_sum(s);
    float inv = 1.f / s;
    #pragma unroll
    for (int r = 0; r < 8; r++) {
        int j = threadIdx.x + r * 256;
        row[j] = v[r] * inv;
    }
}

// ---------------- SwiGLU ----------------
__global__ void swiglu_kernel(float* __restrict__ g, const float* __restrict__ u, int n4) {
    int idx = blockIdx.x * blockDim.x + threadIdx.x;
    int stride = gridDim.x * blockDim.x;
    for (; idx < n4; idx += stride) {
        float4 gv = ((float4*)g)[idx];
        float4 uv = ((const float4*)u)[idx];
        gv.x = gv.x / (1.f + expf(-gv.x)) * uv.x;
        gv.y = gv.y / (1.f + expf(-gv.y)) * uv.y;
        gv.z = gv.z / (1.f + expf(-gv.z)) * uv.z;
        gv.w = gv.w / (1.f + expf(-gv.w)) * uv.w;
        ((float4*)g)[idx] = gv;
    }
}

// ---------------- TF32 tensor-core GEMM ----------------
// C[M,N] = alpha * A[M,K] @ op(B) (+ Res)
//   B_KN=false: B is [N,K] row-major (weights / K matrix, "NT")
//   B_KN=true : B is [K,N] row-major (PV, "NN")
// BK fixed at 16 (two k=8 mma steps). cp.async double-buffered smem.
// Warp layout: (BM/WM) x (BN/WN) warps; warp tile WM x WN (WM%16==0, WN%8==0).
template<int BM, int BN, int WM, int WN, bool B_KN, bool ADD_RES, bool CAUSAL>
__global__ void __launch_bounds__((BM/WM)*(BN/WN)*32)
mma_gemm(const float* __restrict__ A, int lda,
         const float* __restrict__ B, int ldb,
         float* __restrict__ C, int ldc,
         const float* __restrict__ Res,
         int M, int N, int K, float alpha,
         long long sAb, long long sAh,
         long long sBb, long long sBh,
         long long sCb, long long sCh) {
    constexpr int BK = 16;
    constexpr int WARPS_N = BN / WN;
    constexpr int THREADS = (BM/WM) * (BN/WN) * 32;
    constexpr int MFRAG = WM / 16;
    constexpr int NFRAG = WN / 8;
    constexpr int APITCH = BK + 4;          // 20 floats, conflict-free, 16B-aligned rows
    constexpr int BPITCH_NT = BK + 4;       // Bs[n][k]
    constexpr int BPITCH_KN = BN + 8;       // Bs[k][n]
    constexpr int ASIZE = BM * APITCH;
    constexpr int BSIZE = B_KN ? BK * BPITCH_KN : BN * BPITCH_NT;

    const int bx = blockIdx.x, by = blockIdx.y;
    if (CAUSAL && (long long)bx * BN > (long long)by * BM + (BM - 1)) return;

    const int zb = blockIdx.z >> 4, zh = blockIdx.z & 15;
    A += zb * sAb + zh * sAh;
    B += zb * sBb + zh * sBh;
    C += zb * sCb + zh * sCh;
    if (ADD_RES) Res += zb * sCb + zh * sCh;

    __shared__ float As[2][ASIZE];
    __shared__ float Bs[2][BSIZE];

    const int tid  = threadIdx.x;
    const int lane = tid & 31;
    const int wid  = tid >> 5;
    const int wm_base = (wid / WARPS_N) * WM;
    const int wn_base = (wid % WARPS_N) * WN;
    const int m0 = by * BM, n0 = bx * BN;
    const int lr = lane >> 2;   // 0..7
    const int lc = lane & 3;    // 0..3

    float acc[MFRAG][NFRAG][4];
    #pragma unroll
    for (int i = 0; i < MFRAG; i++)
        #pragma unroll
        for (int j = 0; j < NFRAG; j++)
            #pragma unroll
            for (int r = 0; r < 4; r++) acc[i][j][r] = 0.f;

    const int ntiles = K / BK;

    auto load_tile = [&](int buf, int kt) {
        uint32_t as_u = (uint32_t)__cvta_generic_to_shared(&As[buf][0]);
        uint32_t bs_u = (uint32_t)__cvta_generic_to_shared(&Bs[buf][0]);
        // A tile: BM rows x 16 cols = BM*4 16B chunks
        #pragma unroll
        for (int c = tid; c < BM * 4; c += THREADS) {
            int row = c >> 2, kc = c & 3;
            cp16(as_u + (uint32_t)(row * APITCH + kc * 4) * 4,
                 A + (size_t)(m0 + row) * lda + kt + kc * 4);
        }
        if (!B_KN) {
            #pragma unroll
            for (int c = tid; c < BN * 4; c += THREADS) {
                int row = c >> 2, kc = c & 3;
                cp16(bs_u + (uint32_t)(row * BPITCH_NT + kc * 4) * 4,
                     B + (size_t)(n0 + row) * ldb + kt + kc * 4);
            }
        } else {
            constexpr int NC = BN / 4;
            #pragma unroll
            for (int c = tid; c < BK * NC; c += THREADS) {
                int row = c / NC, nc = c % NC;
                cp16(bs_u + (uint32_t)(row * BPITCH_KN + nc * 4) * 4,
                     B + (size_t)(kt + row) * ldb + n0 + nc * 4);
            }
        }
    };

    load_tile(0, 0);
    asm volatile("cp.async.commit_group;");

    for (int t = 0; t < ntiles; t++) {
        if (t + 1 < ntiles) {
            load_tile((t + 1) & 1, (t + 1) * BK);
            asm volatile("cp.async.commit_group;");
            asm volatile("cp.async.wait_group 1;");
        } else {
            asm volatile("cp.async.wait_group 0;");
        }
        __syncthreads();

        const float* as = As[t & 1];
        const float* bs = Bs[t & 1];
        #pragma unroll
        for (int ks = 0; ks < 2; ks++) {
            const int k0 = ks * 8;
            uint32_t af[MFRAG][4];
            uint32_t bf[NFRAG][2];
            #pragma unroll
            for (int mi = 0; mi < MFRAG; mi++) {
                int mr = wm_base + mi * 16 + lr;
                af[mi][0] = f2tf32(as[(mr    ) * APITCH + k0 + lc    ]);
                af[mi][1] = f2tf32(as[(mr + 8) * APITCH + k0 + lc    ]);
                af[mi][2] = f2tf32(as[(mr    ) * APITCH + k0 + lc + 4]);
                af[mi][3] = f2tf32(as[(mr + 8) * APITCH + k0 + lc + 4]);
            }
            #pragma unroll
            for (int nj = 0; nj < NFRAG; nj++) {
                if (!B_KN) {
                    int nr = wn_base + nj * 8 + lr;
                    bf[nj][0] = f2tf32(bs[nr * BPITCH_NT + k0 + lc    ]);
                    bf[nj][1] = f2tf32(bs[nr * BPITCH_NT + k0 + lc + 4]);
                } else {
                    int nc = wn_base + nj * 8 + lr;
                    bf[nj][0] = f2tf32(bs[(k0 + lc    ) * BPITCH_KN + nc]);
                    bf[nj][1] = f2tf32(bs[(k0 + lc + 4) * BPITCH_KN + nc]);
                }
            }
            #pragma unroll
            for (int mi = 0; mi < MFRAG; mi++)
                #pragma unroll
                for (int nj = 0; nj < NFRAG; nj++)
                    mma_tf32(acc[mi][nj][0], acc[mi][nj][1], acc[mi][nj][2], acc[mi][nj][3],
                             af[mi][0], af[mi][1], af[mi][2], af[mi][3],
                             bf[nj][0], bf[nj][1]);
        }
        __syncthreads();
    }

    // epilogue: c0,c1 at (row, 2*lc), c2,c3 at (row+8, 2*lc)
    #pragma unroll
    for (int mi = 0; mi < MFRAG; mi++) {
        int gm = m0 + wm_base + mi * 16 + lr;
        #pragma unroll
        for (int nj = 0; nj < NFRAG; nj++) {
            int gn = n0 + wn_base + nj * 8 + 2 * lc;
            float2 v0 = make_float2(acc[mi][nj][0] * alpha, acc[mi][nj][1] * alpha);
            float2 v1 = make_float2(acc[mi][nj][2] * alpha, acc[mi][nj][3] * alpha);
            if (ADD_RES) {
                float2 r0 = *(const float2*)(Res + (size_t)gm * ldc + gn);
                float2 r1 = *(const float2*)(Res + (size_t)(gm + 8) * ldc + gn);
                v0.x += r0.x; v0.y += r0.y;
                v1.x += r1.x; v1.y += r1.y;
            }
            *(float2*)(C + (size_t)gm * ldc + gn) = v0;
            *(float2*)(C + (size_t)(gm + 8) * ldc + gn) = v1;
        }
    }
}

// ---------------- launch ----------------
extern "C" void kernel_launch(void* const* d_in, const int* in_sizes, int n_in,
                              void* d_out, int out_size) {
    const float* x      = (const float*)d_in[0];
    const float* w_ln1  = (const float*)d_in[1];
    const float* w_qkv  = (const float*)d_in[2];
    const float* w_out  = (const float*)d_in[3];
    const float* w_ln2  = (const float*)d_in[4];
    const float* w_gate = (const float*)d_in[5];
    const float* w_up   = (const float*)d_in[6];
    const float* w_down = (const float*)d_in[7];
    float* out = (float*)d_out;

    void* p;
    cudaGetSymbolAddress(&p, g_h);    float* h    = (float*)p;
    cudaGetSymbolAddress(&p, g_qkv);  float* qkv  = (float*)p;
    cudaGetSymbolAddress(&p, g_S);    float* S    = (float*)p;
    cudaGetSymbolAddress(&p, g_attn); float* attn = (float*)p;
    cudaGetSymbolAddress(&p, g_x2);   float* x2   = (float*)p;
    cudaGetSymbolAddress(&p, g_gate); float* gate = (float*)p;
    cudaGetSymbolAddress(&p, g_up);   float* up   = (float*)p;

    const long long z0 = 0;

    // 1) h = rmsnorm(x, w_ln1)
    rmsnorm_kernel<<<NTOK, 256>>>(x, w_ln1, h);

    // 2) qkv = h @ w_qkv^T
    mma_gemm<128,128,64,32,false,false,false>
        <<<dim3(3*TOT/128, NTOK/128, 1), 256>>>(
        h, D_MODEL, w_qkv, D_MODEL, qkv, 3*TOT, nullptr,
        NTOK, 3*TOT, D_MODEL, 1.f, z0, z0, z0, z0, z0, z0);

    // 3) RoPE
    rope_kernel<<<NTOK, 512>>>(qkv);

    // 4) S = scale * Q @ K^T per (b,h), causal block-skip
    mma_gemm<128,128,64,32,false,false,true>
        <<<dim3(SEQ/128, SEQ/128, BATCH*NH), 256>>>(
        qkv, 3*TOT, qkv + TOT, 3*TOT, S, SEQ, nullptr,
        SEQ, SEQ, DH, 0.125f,
        (long long)SEQ*3*TOT, DH,
        (long long)SEQ*3*TOT, DH,
        (long long)NH*SEQ*SEQ, (long long)SEQ*SEQ);

    // 5) causal softmax (zeros above diagonal)
    softmax_causal_kernel<<<dim3(SEQ, BATCH*NH), 256>>>(S);

    // 6) attn = P @ V  (NN)
    mma_gemm<128,64,32,32,true,false,false>
        <<<dim3(1, SEQ/128, BATCH*NH), 256>>>(
        S, SEQ, qkv + 2*TOT, 3*TOT, attn, TOT, nullptr,
        SEQ, DH, SEQ, 1.f,
        (long long)NH*SEQ*SEQ, (long long)SEQ*SEQ,
        (long long)SEQ*3*TOT, DH,
        (long long)SEQ*TOT, DH);

    // 7) x2 = x + attn @ w_out^T
    mma_gemm<128,128,64,32,false,true,false>
        <<<dim3(D_MODEL/128, NTOK/128, 1), 256>>>(
        attn, TOT, w_out, TOT, x2, D_MODEL, x,
        NTOK, D_MODEL, TOT, 1.f, z0, z0, z0, z0, z0, z0);

    // 8) h = rmsnorm(x2, w_ln2)
    rmsnorm_kernel<<<NTOK, 256>>>(x2, w_ln2, h);

    // 9) gate/up projections
    mma_gemm<128,128,64,32,false,false,false>
        <<<dim3(D_FF/128, NTOK/128, 1), 256>>>(
        h, D_MODEL, w_gate, D_MODEL, gate, D_FF, nullptr,
        NTOK, D_FF, D_MODEL, 1.f, z0, z0, z0, z0, z0, z0);
    mma_gemm<128,128,64,32,false,false,false>
        <<<dim3(D_FF/128, NTOK/128, 1), 256>>>(
        h, D_MODEL, w_up, D_MODEL, up, D_FF, nullptr,
        NTOK, D_FF, D_MODEL, 1.f, z0, z0, z0, z0, z0, z0);

    // 10) gate = silu(gate) * up
    swiglu_kernel<<<4096, 256>>>(gate, up, NTOK * D_FF / 4);

    // 11) out = x2 + gate @ w_down^T
    mma_gemm<128,128,64,32,false,true,false>
        <<<dim3(D_MODEL/128, NTOK/128, 1), 256>>>(
        gate, D_FF, w_down, D_FF, out, D_MODEL, x2,
        NTOK, D_MODEL, D_FF, 1.f, z0, z0, z0, z0, z0, z0);
}

// round 3
// speedup vs baseline: 3.1634x; 1.0000x over previous
#include <cuda_runtime.h>
#include <math.h>
#include <stdint.h>

// ---------------- problem constants ----------------
#define D_MODEL 1024
#define D_FF    4096
#define NH      16
#define DH      64
#define TOT     1024          // NH*DH
#define BATCH   2
#define SEQ     2048
#define NTOK    (BATCH*SEQ)   // 4096

// ---------------- scratch (device globals: allocation-free) ----------------
__device__ float g_h   [(size_t)NTOK * D_MODEL];
__device__ float g_qkv [(size_t)NTOK * 3 * TOT];
__device__ float g_S   [(size_t)BATCH * NH * SEQ * SEQ];
__device__ float g_attn[(size_t)NTOK * TOT];
__device__ float g_x2  [(size_t)NTOK * D_MODEL];
__device__ float g_gate[(size_t)NTOK * D_FF];
__device__ float g_up  [(size_t)NTOK * D_FF];

// ---------------- small helpers ----------------
__device__ __forceinline__ void cp16(uint32_t dst, const void* src) {
    asm volatile("cp.async.cg.shared.global [%0], [%1], 16;" :: "r"(dst), "l"(src));
}
__device__ __forceinline__ uint32_t f2tf32(float f) {
    uint32_t r;
    asm("cvt.rna.tf32.f32 %0, %1;" : "=r"(r) : "f"(f));
    return r;
}
__device__ __forceinline__ void mma_tf32(float& c0, float& c1, float& c2, float& c3,
                                         uint32_t a0, uint32_t a1, uint32_t a2, uint32_t a3,
                                         uint32_t b0, uint32_t b1) {
    asm volatile(
        "mma.sync.aligned.m16n8k8.row.col.f32.tf32.tf32.f32 "
        "{%0,%1,%2,%3}, {%4,%5,%6,%7}, {%8,%9}, {%0,%1,%2,%3};"
        : "+f"(c0), "+f"(c1), "+f"(c2), "+f"(c3)
        : "r"(a0), "r"(a1), "r"(a2), "r"(a3), "r"(b0), "r"(b1));
}

// ---------------- block reductions (256 threads) ----------------
__device__ __forceinline__ float block_reduce_sum(float v) {
    __shared__ float sh[33];
    int lane = threadIdx.x & 31, wid = threadIdx.x >> 5;
    #pragma unroll
    for (int o = 16; o; o >>= 1) v += __shfl_xor_sync(0xffffffffu, v, o);
    if (lane == 0) sh[wid] = v;
    __syncthreads();
    if (wid == 0) {
        v = (lane < (blockDim.x >> 5)) ? sh[lane] : 0.f;
        #pragma unroll
        for (int o = 16; o; o >>= 1) v += __shfl_xor_sync(0xffffffffu, v, o);
        if (lane == 0) sh[32] = v;
    }
    __syncthreads();
    float r = sh[32];
    __syncthreads();
    return r;
}

__device__ __forceinline__ float block_reduce_max(float v) {
    __shared__ float sh[33];
    int lane = threadIdx.x & 31, wid = threadIdx.x >> 5;
    #pragma unroll
    for (int o = 16; o; o >>= 1) v = fmaxf(v, __shfl_xor_sync(0xffffffffu, v, o));
    if (lane == 0) sh[wid] = v;
    __syncthreads();
    if (wid == 0) {
        v = (lane < (blockDim.x >> 5)) ? sh[lane] : -1e30f;
        #pragma unroll
        for (int o = 16; o; o >>= 1) v = fmaxf(v, __shfl_xor_sync(0xffffffffu, v, o));
        if (lane == 0) sh[32] = v;
    }
    __syncthreads();
    float r = sh[32];
    __syncthreads();
    return r;
}

// ---------------- RMSNorm ----------------
__global__ void rmsnorm_kernel(const float* __restrict__ x,
                               const float* __restrict__ w,
                               float* __restrict__ o) {
    const size_t base = (size_t)blockIdx.x * D_MODEL;
    float ss = 0.f;
    for (int i = threadIdx.x; i < D_MODEL; i += 256) {
        float v = x[base + i];
        ss += v * v;
    }
    ss = block_reduce_sum(ss);
    float r = rsqrtf(ss * (1.0f / D_MODEL) + 1e-6f);
    for (int i = threadIdx.x; i < D_MODEL; i += 256)
        o[base + i] = x[base + i] * r * w[i];
}

// ---------------- RoPE in-place on q,k parts of qkv ----------------
__global__ void rope_kernel(float* __restrict__ qkv) {
    const int t   = blockIdx.x;
    const int pos = t & (SEQ - 1);
    const int h   = threadIdx.x >> 5;
    const int i   = threadIdx.x & 31;
    float invf = expf(-(2.0f * (float)i / (float)DH) * logf(10000.0f));
    float fr = (float)pos * invf;
    float s, c;
    sincosf(fr, &s, &c);
    float* q = qkv + (size_t)t * (3 * TOT) + h * DH;
    float q1 = q[i], q2 = q[i + 32];
    q[i]      = q1 * c - q2 * s;
    q[i + 32] = q2 * c + q1 * s;
    float* k = q + TOT;
    float k1 = k[i], k2 = k[i + 32];
    k[i]      = k1 * c - k2 * s;
    k[i + 32] = k2 * c + k1 * s;
}

// ---------------- causal row softmax ----------------
__global__ void softmax_causal_kernel(float* __restrict__ S) {
    const int i  = blockIdx.x;
    const int bh = blockIdx.y;
    float* row = S + ((size_t)bh * SEQ + i) * SEQ;
    const int L = i + 1;
    float v[8];
    float m = -1e30f;
    #pragma unroll
    for (int r = 0; r < 8; r++) {
        int j = threadIdx.x + r * 256;
        v[r] = (j < L) ? row[j] : -1e30f;
        m = fmaxf(m, v[r]);
    }
    m = block_reduce_max(m);
    float s = 0.f;
    #pragma unroll
    for (int r = 0; r < 8; r++) {
        int j = threadIdx.x + r * 256;
        v[r] = (j < L) ? expf(v[r] - m) : 0.f;
        s += v[r];
    }
    s = block_reduce_sum(s);
    float inv = 1.f / s;
    #pragma unroll
    for (int r = 0; r < 8; r++) {
        int j = threadIdx.x + r * 256;
        row[j] = v[r] * inv;
    }
}

// ---------------- SwiGLU ----------------
__global__ void swiglu_kernel(float* __restrict__ g, const float* __restrict__ u, int n4) {
    int idx = blockIdx.x * blockDim.x + threadIdx.x;
    int stride = gridDim.x * blockDim.x;
    for (; idx < n4; idx += stride) {
        float4 gv = ((float4*)g)[idx];
        float4 uv = ((const float4*)u)[idx];
        gv.x = gv.x / (1.f + expf(-gv.x)) * uv.x;
        gv.y = gv.y / (1.f + expf(-gv.y)) * uv.y;
        gv.z = gv.z / (1.f + expf(-gv.z)) * uv.z;
        gv.w = gv.w / (1.f + expf(-gv.w)) * uv.w;
        ((float4*)g)[idx] = gv;
    }
}

// ---------------- TF32 tensor-core GEMM ----------------
// C[M,N] = alpha * A[M,K] @ op(B) (+ Res)
//   B_KN=false: B is [N,K] row-major (weights / K matrix, "NT")
//   B_KN=true : B is [K,N] row-major (PV, "NN")
// BK fixed at 16 (two k=8 mma steps). cp.async double-buffered smem.
// Warp layout: (BM/WM) x (BN/WN) warps; warp tile WM x WN (WM%16==0, WN%8==0).
template<int BM, int BN, int WM, int WN, bool B_KN, bool ADD_RES, bool CAUSAL>
__global__ void __launch_bounds__((BM/WM)*(BN/WN)*32)
mma_gemm(const float* __restrict__ A, int lda,
         const float* __restrict__ B, int ldb,
         float* __restrict__ C, int ldc,
         const float* __restrict__ Res,
         int M, int N, int K, float alpha,
         long long sAb, long long sAh,
         long long sBb, long long sBh,
         long long sCb, long long sCh) {
    constexpr int BK = 16;
    constexpr int WARPS_N = BN / WN;
    constexpr int THREADS = (BM/WM) * (BN/WN) * 32;
    constexpr int MFRAG = WM / 16;
    constexpr int NFRAG = WN / 8;
    constexpr int APITCH = BK + 4;          // 20 floats, conflict-free, 16B-aligned rows
    constexpr int BPITCH_NT = BK + 4;       // Bs[n][k]
    constexpr int BPITCH_KN = BN + 8;       // Bs[k][n]
    constexpr int ASIZE = BM * APITCH;
    constexpr int BSIZE = B_KN ? BK * BPITCH_KN : BN * BPITCH_NT;

    const int bx = blockIdx.x, by = blockIdx.y;
    if (CAUSAL && (long long)bx * BN > (long long)by * BM + (BM - 1)) return;

    const int zb = blockIdx.z >> 4, zh = blockIdx.z & 15;
    A += zb * sAb + zh * sAh;
    B += zb * sBb + zh * sBh;
    C += zb * sCb + zh * sCh;
    if (ADD_RES) Res += zb * sCb + zh * sCh;

    __shared__ float As[2][ASIZE];
    __shared__ float Bs[2][BSIZE];

    const int tid  = threadIdx.x;
    const int lane = tid & 31;
    const int wid  = tid >> 5;
    const int wm_base = (wid / WARPS_N) * WM;
    const int wn_base = (wid % WARPS_N) * WN;
    const int m0 = by * BM, n0 = bx * BN;
    const int lr = lane >> 2;   // 0..7
    const int lc = lane & 3;    // 0..3

    float acc[MFRAG][NFRAG][4];
    #pragma unroll
    for (int i = 0; i < MFRAG; i++)
        #pragma unroll
        for (int j = 0; j < NFRAG; j++)
            #pragma unroll
            for (int r = 0; r < 4; r++) acc[i][j][r] = 0.f;

    const int ntiles = K / BK;

    auto load_tile = [&](int buf, int kt) {
        uint32_t as_u = (uint32_t)__cvta_generic_to_shared(&As[buf][0]);
        uint32_t bs_u = (uint32_t)__cvta_generic_to_shared(&Bs[buf][0]);
        // A tile: BM rows x 16 cols = BM*4 16B chunks
        #pragma unroll
        for (int c = tid; c < BM * 4; c += THREADS) {
            int row = c >> 2, kc = c & 3;
            cp16(as_u + (uint32_t)(row * APITCH + kc * 4) * 4,
                 A + (size_t)(m0 + row) * lda + kt + kc * 4);
        }
        if (!B_KN) {
            #pragma unroll
            for (int c = tid; c < BN * 4; c += THREADS) {
                int row = c >> 2, kc = c & 3;
                cp16(bs_u + (uint32_t)(row * BPITCH_NT + kc * 4) * 4,
                     B + (size_t)(n0 + row) * ldb + kt + kc * 4);
            }
        } else {
            constexpr int NC = BN / 4;
            #pragma unroll
            for (int c = tid; c < BK * NC; c += THREADS) {
                int row = c / NC, nc = c % NC;
                cp16(bs_u + (uint32_t)(row * BPITCH_KN + nc * 4) * 4,
                     B + (size_t)(kt + row) * ldb + n0 + nc * 4);
            }
        }
    };

    load_tile(0, 0);
    asm volatile("cp.async.commit_group;");

    for (int t = 0; t < ntiles; t++) {
        if (t + 1 < ntiles) {
            load_tile((t + 1) & 1, (t + 1) * BK);
            asm volatile("cp.async.commit_group;");
            asm volatile("cp.async.wait_group 1;");
        } else {
            asm volatile("cp.async.wait_group 0;");
        }
        __syncthreads();

        const float* as = As[t & 1];
        const float* bs = Bs[t & 1];
        #pragma unroll
        for (int ks = 0; ks < 2; ks++) {
            const int k0 = ks * 8;
            uint32_t af[MFRAG][4];
            uint32_t bf[NFRAG][2];
            #pragma unroll
            for (int mi = 0; mi < MFRAG; mi++) {
                int mr = wm_base + mi * 16 + lr;
                af[mi][0] = f2tf32(as[(mr    ) * APITCH + k0 + lc    ]);
                af[mi][1] = f2tf32(as[(mr + 8) * APITCH + k0 + lc    ]);
                af[mi][2] = f2tf32(as[(mr    ) * APITCH + k0 + lc + 4]);
                af[mi][3] = f2tf32(as[(mr + 8) * APITCH + k0 + lc + 4]);
            }
            #pragma unroll
            for (int nj = 0; nj < NFRAG; nj++) {
                if (!B_KN) {
                    int nr = wn_base + nj * 8 + lr;
                    bf[nj][0] = f2tf32(bs[nr * BPITCH_NT + k0 + lc    ]);
                    bf[nj][1] = f2tf32(bs[nr * BPITCH_NT + k0 + lc + 4]);
                } else {
                    int nc = wn_base + nj * 8 + lr;
                    bf[nj][0] = f2tf32(bs[(k0 + lc    ) * BPITCH_KN + nc]);
                    bf[nj][1] = f2tf32(bs[(k0 + lc + 4) * BPITCH_KN + nc]);
                }
            }
            #pragma unroll
            for (int mi = 0; mi < MFRAG; mi++)
                #pragma unroll
                for (int nj = 0; nj < NFRAG; nj++)
                    mma_tf32(acc[mi][nj][0], acc[mi][nj][1], acc[mi][nj][2], acc[mi][nj][3],
                             af[mi][0], af[mi][1], af[mi][2], af[mi][3],
                             bf[nj][0], bf[nj][1]);
        }
        __syncthreads();
    }

    // epilogue: c0,c1 at (row, 2*lc), c2,c3 at (row+8, 2*lc)
    #pragma unroll
    for (int mi = 0; mi < MFRAG; mi++) {
        int gm = m0 + wm_base + mi * 16 + lr;
        #pragma unroll
        for (int nj = 0; nj < NFRAG; nj++) {
            int gn = n0 + wn_base + nj * 8 + 2 * lc;
            float2 v0 = make_float2(acc[mi][nj][0] * alpha, acc[mi][nj][1] * alpha);
            float2 v1 = make_float2(acc[mi][nj][2] * alpha, acc[mi][nj][3] * alpha);
            if (ADD_RES) {
                float2 r0 = *(const float2*)(Res + (size_t)gm * ldc + gn);
                float2 r1 = *(const float2*)(Res + (size_t)(gm + 8) * ldc + gn);
                v0.x += r0.x; v0.y += r0.y;
                v1.x += r1.x; v1.y += r1.y;
            }
            *(float2*)(C + (size_t)gm * ldc + gn) = v0;
            *(float2*)(C + (size_t)(gm + 8) * ldc + gn) = v1;
        }
    }
}

// ---------------- launch ----------------
extern "C" void kernel_launch(void* const* d_in, const int* in_sizes, int n_in,
                              void* d_out, int out_size) {
    const float* x      = (const float*)d_in[0];
    const float* w_ln1  = (const float*)d_in[1];
    const float* w_qkv  = (const float*)d_in[2];
    const float* w_out  = (const float*)d_in[3];
    const float* w_ln2  = (const float*)d_in[4];
    const float* w_gate = (const float*)d_in[5];
    const float* w_up   = (const float*)d_in[6];
    const float* w_down = (const float*)d_in[7];
    float* out = (float*)d_out;

    void* p;
    cudaGetSymbolAddress(&p, g_h);    float* h    = (float*)p;
    cudaGetSymbolAddress(&p, g_qkv);  float* qkv  = (float*)p;
    cudaGetSymbolAddress(&p, g_S);    float* S    = (float*)p;
    cudaGetSymbolAddress(&p, g_attn); float* attn = (float*)p;
    cudaGetSymbolAddress(&p, g_x2);   float* x2   = (float*)p;
    cudaGetSymbolAddress(&p, g_gate); float* gate = (float*)p;
    cudaGetSymbolAddress(&p, g_up);   float* up   = (float*)p;

    const long long z0 = 0;

    // 1) h = rmsnorm(x, w_ln1)
    rmsnorm_kernel<<<NTOK, 256>>>(x, w_ln1, h);

    // 2) qkv = h @ w_qkv^T
    mma_gemm<128,128,64,32,false,false,false>
        <<<dim3(3*TOT/128, NTOK/128, 1), 256>>>(
        h, D_MODEL, w_qkv, D_MODEL, qkv, 3*TOT, nullptr,
        NTOK, 3*TOT, D_MODEL, 1.f, z0, z0, z0, z0, z0, z0);

    // 3) RoPE
    rope_kernel<<<NTOK, 512>>>(qkv);

    // 4) S = scale * Q @ K^T per (b,h), causal block-skip
    mma_gemm<128,128,64,32,false,false,true>
        <<<dim3(SEQ/128, SEQ/128, BATCH*NH), 256>>>(
        qkv, 3*TOT, qkv + TOT, 3*TOT, S, SEQ, nullptr,
        SEQ, SEQ, DH, 0.125f,
        (long long)SEQ*3*TOT, DH,
        (long long)SEQ*3*TOT, DH,
        (long long)NH*SEQ*SEQ, (long long)SEQ*SEQ);

    // 5) causal softmax (zeros above diagonal)
    softmax_causal_kernel<<<dim3(SEQ, BATCH*NH), 256>>>(S);

    // 6) attn = P @ V  (NN)
    mma_gemm<128,64,32,32,true,false,false>
        <<<dim3(1, SEQ/128, BATCH*NH), 256>>>(
        S, SEQ, qkv + 2*TOT, 3*TOT, attn, TOT, nullptr,
        SEQ, DH, SEQ, 1.f,
        (long long)NH*SEQ*SEQ, (long long)SEQ*SEQ,
        (long long)SEQ*3*TOT, DH,
        (long long)SEQ*TOT, DH);

    // 7) x2 = x + attn @ w_out^T
    mma_gemm<128,128,64,32,false,true,false>
        <<<dim3(D_MODEL/128, NTOK/128, 1), 256>>>(
        attn, TOT, w_out, TOT, x2, D_MODEL, x,
        NTOK, D_MODEL, TOT, 1.f, z0, z0, z0, z0, z0, z0);

    // 8) h = rmsnorm(x2, w_ln2)
    rmsnorm_kernel<<<NTOK, 256>>>(x2, w_ln2, h);

    // 9) gate/up projections
    mma_gemm<128,128,64,32,false,false,false>
        <<<dim3(D_FF/128, NTOK/128, 1), 256>>>(
        h, D_MODEL, w_gate, D_MODEL, gate, D_FF, nullptr,
        NTOK, D_FF, D_MODEL, 1.f, z0, z0, z0, z0, z0, z0);
    mma_gemm<128,128,64,32,false,false,false>
        <<<dim3(D_FF/128, NTOK/128, 1), 256>>>(
        h, D_MODEL, w_up, D_MODEL, up, D_FF, nullptr,
        NTOK, D_FF, D_MODEL, 1.f, z0, z0, z0, z0, z0, z0);

    // 10) gate = silu(gate) * up
    swiglu_kernel<<<4096, 256>>>(gate, up, NTOK * D_FF / 4);

    // 11) out = x2 + gate @ w_down^T
    mma_gemm<128,128,64,32,false,true,false>
        <<<dim3(D_MODEL/128, NTOK/128, 1), 256>>>(
        gate, D_FF, w_down, D_FF, out, D_MODEL, x2,
        NTOK, D_MODEL, D_FF, 1.f, z0, z0, z0, z0, z0, z0);
}

// round 5
// speedup vs baseline: 3.6919x; 1.1671x over previous
#include <cuda_runtime.h>
#include <math.h>
#include <stdint.h>

// ---------------- problem constants ----------------
#define D_MODEL 1024
#define D_FF    4096
#define NH      16
#define DH      64
#define TOT     1024
#define BATCH   2
#define SEQ     2048
#define NTOK    (BATCH*SEQ)

// ---------------- scratch ----------------
__device__ float g_h   [(size_t)NTOK * D_MODEL];
__device__ float g_qkv [(size_t)NTOK * 3 * TOT];
__device__ float g_attn[(size_t)NTOK * TOT];
__device__ float g_x2  [(size_t)NTOK * D_MODEL];
__device__ float g_gate[(size_t)NTOK * D_FF];
__device__ float g_up  [(size_t)NTOK * D_FF];
__device__ float g_wc  [(size_t)16 * 1024 * 1024];   // tf32-rounded weights

// ---------------- helpers ----------------
__device__ __forceinline__ void cp16(uint32_t dst, const void* src) {
    asm volatile("cp.async.cg.shared.global [%0], [%1], 16;" :: "r"(dst), "l"(src));
}
__device__ __forceinline__ uint32_t f2tf32(float f) {
    uint32_t r;
    asm("cvt.rna.tf32.f32 %0, %1;" : "=r"(r) : "f"(f));
    return r;
}
__device__ __forceinline__ float tf32r(float f) { return __uint_as_float(f2tf32(f)); }
__device__ __forceinline__ float ex2(float x) {
    float r;
    asm("ex2.approx.ftz.f32 %0, %1;" : "=f"(r) : "f"(x));
    return r;
}
__device__ __forceinline__ void mma_tf32(float& c0, float& c1, float& c2, float& c3,
                                         uint32_t a0, uint32_t a1, uint32_t a2, uint32_t a3,
                                         uint32_t b0, uint32_t b1) {
    asm volatile(
        "mma.sync.aligned.m16n8k8.row.col.f32.tf32.tf32.f32 "
        "{%0,%1,%2,%3}, {%4,%5,%6,%7}, {%8,%9}, {%0,%1,%2,%3};"
        : "+f"(c0), "+f"(c1), "+f"(c2), "+f"(c3)
        : "r"(a0), "r"(a1), "r"(a2), "r"(a3), "r"(b0), "r"(b1));
}

__device__ __forceinline__ float block_reduce_sum(float v) {
    __shared__ float sh[33];
    int lane = threadIdx.x & 31, wid = threadIdx.x >> 5;
    #pragma unroll
    for (int o = 16; o; o >>= 1) v += __shfl_xor_sync(0xffffffffu, v, o);
    if (lane == 0) sh[wid] = v;
    __syncthreads();
    if (wid == 0) {
        v = (lane < (blockDim.x >> 5)) ? sh[lane] : 0.f;
        #pragma unroll
        for (int o = 16; o; o >>= 1) v += __shfl_xor_sync(0xffffffffu, v, o);
        if (lane == 0) sh[32] = v;
    }
    __syncthreads();
    float r = sh[32];
    __syncthreads();
    return r;
}

// ---------------- tf32 rounding pass (weights) ----------------
__global__ void round_tf32_kernel(const float* __restrict__ in, float* __restrict__ out, int n4) {
    int idx = blockIdx.x * blockDim.x + threadIdx.x;
    int stride = gridDim.x * blockDim.x;
    for (; idx < n4; idx += stride) {
        float4 v = ((const float4*)in)[idx];
        v.x = tf32r(v.x); v.y = tf32r(v.y); v.z = tf32r(v.z); v.w = tf32r(v.w);
        ((float4*)out)[idx] = v;
    }
}

// ---------------- RMSNorm (rounded output feeds GEMMs) ----------------
__global__ void rmsnorm_kernel(const float* __restrict__ x,
                               const float* __restrict__ w,
                               float* __restrict__ o) {
    const size_t base = (size_t)blockIdx.x * D_MODEL;
    float ss = 0.f;
    for (int i = threadIdx.x; i < D_MODEL; i += 256) {
        float v = x[base + i];
        ss += v * v;
    }
    ss = block_reduce_sum(ss);
    float r = rsqrtf(ss * (1.0f / D_MODEL) + 1e-6f);
    for (int i = threadIdx.x; i < D_MODEL; i += 256)
        o[base + i] = tf32r(x[base + i] * r * w[i]);
}

// ---------------- RoPE (rounded q,k) ----------------
__global__ void rope_kernel(float* __restrict__ qkv) {
    const int t   = blockIdx.x;
    const int pos = t & (SEQ - 1);
    const int h   = threadIdx.x >> 5;
    const int i   = threadIdx.x & 31;
    float invf = expf(-(2.0f * (float)i / (float)DH) * logf(10000.0f));
    float fr = (float)pos * invf;
    float s, c;
    sincosf(fr, &s, &c);
    float* q = qkv + (size_t)t * (3 * TOT) + h * DH;
    float q1 = q[i], q2 = q[i + 32];
    q[i]      = tf32r(q1 * c - q2 * s);
    q[i + 32] = tf32r(q2 * c + q1 * s);
    float* k = q + TOT;
    float k1 = k[i], k2 = k[i + 32];
    k[i]      = tf32r(k1 * c - k2 * s);
    k[i + 32] = tf32r(k2 * c + k1 * s);
}

// ---------------- SwiGLU (rounded output feeds down-proj) ----------------
__global__ void swiglu_kernel(float* __restrict__ g, const float* __restrict__ u, int n4) {
    int idx = blockIdx.x * blockDim.x + threadIdx.x;
    int stride = gridDim.x * blockDim.x;
    for (; idx < n4; idx += stride) {
        float4 gv = ((float4*)g)[idx];
        float4 uv = ((const float4*)u)[idx];
        gv.x = tf32r(gv.x / (1.f + __expf(-gv.x)) * uv.x);
        gv.y = tf32r(gv.y / (1.f + __expf(-gv.y)) * uv.y);
        gv.z = tf32r(gv.z / (1.f + __expf(-gv.z)) * uv.z);
        gv.w = tf32r(gv.w / (1.f + __expf(-gv.w)) * uv.w);
        ((float4*)g)[idx] = gv;
    }
}

// ---------------- 3-stage TF32 GEMM (NT): C = A @ B^T (+Res) ----------------
// Operands pre-rounded to tf32; no cvt in mainloop.
template<bool ADD_RES, bool ROUND_C>
__global__ void __launch_bounds__(256, 2)
mma_gemm3(const float* __restrict__ A, int lda,
          const float* __restrict__ B, int ldb,
          float* __restrict__ C, int ldc,
          const float* __restrict__ Res, int K) {
    constexpr int BM = 128, BN = 128, BK = 16, WM = 64, WN = 32;
    constexpr int PITCH = 20;              // conflict-free, 16B-aligned rows
    constexpr int ASIZE = BM * PITCH;      // 2560 floats
    constexpr int STAGES = 3;
    constexpr int WARPS_N = BN / WN;       // 4
    constexpr int MFRAG = WM / 16, NFRAG = WN / 8;

    extern __shared__ float smx[];
    float* As = smx;
    float* Bs = smx + STAGES * ASIZE;

    const int tid  = threadIdx.x;
    const int lane = tid & 31;
    const int wid  = tid >> 5;
    const int wm_base = (wid / WARPS_N) * WM;
    const int wn_base = (wid % WARPS_N) * WN;
    const int m0 = blockIdx.y * BM, n0 = blockIdx.x * BN;
    const int lr = lane >> 2, lc = lane & 3;

    float acc[MFRAG][NFRAG][4];
    #pragma unroll
    for (int i = 0; i < MFRAG; i++)
        #pragma unroll
        for (int j = 0; j < NFRAG; j++)
            #pragma unroll
            for (int r = 0; r < 4; r++) acc[i][j][r] = 0.f;

    const int nt = K / BK;

    auto load_tile = [&](int stg, int kt) {
        uint32_t as_u = (uint32_t)__cvta_generic_to_shared(As + stg * ASIZE);
        uint32_t bs_u = (uint32_t)__cvta_generic_to_shared(Bs + stg * ASIZE);
        #pragma unroll
        for (int c = tid; c < BM * 4; c += 256) {
            int row = c >> 2, kc = c & 3;
            cp16(as_u + (uint32_t)(row * PITCH + kc * 4) * 4,
                 A + (size_t)(m0 + row) * lda + kt + kc * 4);
            cp16(bs_u + (uint32_t)(row * PITCH + kc * 4) * 4,
                 B + (size_t)(n0 + row) * ldb + kt + kc * 4);
        }
        asm volatile("cp.async.commit_group;");
    };

    load_tile(0, 0);
    if (nt > 1) load_tile(1, BK);

    for (int t = 0; t < nt; t++) {
        if (t + 1 < nt) asm volatile("cp.async.wait_group 1;");
        else            asm volatile("cp.async.wait_group 0;");
        __syncthreads();
        if (t + 2 < nt) load_tile((t + 2) % 3, (t + 2) * BK);

        const float* as = As + (t % 3) * ASIZE;
        const float* bs = Bs + (t % 3) * ASIZE;
        #pragma unroll
        for (int ks = 0; ks < 2; ks++) {
            const int k0 = ks * 8;
            uint32_t af[MFRAG][4];
            uint32_t bf[NFRAG][2];
            #pragma unroll
            for (int mi = 0; mi < MFRAG; mi++) {
                int mr = wm_base + mi * 16 + lr;
                af[mi][0] = __float_as_uint(as[(mr    ) * PITCH + k0 + lc    ]);
                af[mi][1] = __float_as_uint(as[(mr + 8) * PITCH + k0 + lc    ]);
                af[mi][2] = __float_as_uint(as[(mr    ) * PITCH + k0 + lc + 4]);
                af[mi][3] = __float_as_uint(as[(mr + 8) * PITCH + k0 + lc + 4]);
            }
            #pragma unroll
            for (int nj = 0; nj < NFRAG; nj++) {
                int nr = wn_base + nj * 8 + lr;
                bf[nj][0] = __float_as_uint(bs[nr * PITCH + k0 + lc    ]);
                bf[nj][1] = __float_as_uint(bs[nr * PITCH + k0 + lc + 4]);
            }
            #pragma unroll
            for (int mi = 0; mi < MFRAG; mi++)
                #pragma unroll
                for (int nj = 0; nj < NFRAG; nj++)
                    mma_tf32(acc[mi][nj][0], acc[mi][nj][1], acc[mi][nj][2], acc[mi][nj][3],
                             af[mi][0], af[mi][1], af[mi][2], af[mi][3],
                             bf[nj][0], bf[nj][1]);
        }
        __syncthreads();
    }

    #pragma unroll
    for (int mi = 0; mi < MFRAG; mi++) {
        int gm = m0 + wm_base + mi * 16 + lr;
        #pragma unroll
        for (int nj = 0; nj < NFRAG; nj++) {
            int gn = n0 + wn_base + nj * 8 + 2 * lc;
            float2 v0 = make_float2(acc[mi][nj][0], acc[mi][nj][1]);
            float2 v1 = make_float2(acc[mi][nj][2], acc[mi][nj][3]);
            if (ADD_RES) {
                float2 r0 = *(const float2*)(Res + (size_t)gm * ldc + gn);
                float2 r1 = *(const float2*)(Res + (size_t)(gm + 8) * ldc + gn);
                v0.x += r0.x; v0.y += r0.y;
                v1.x += r1.x; v1.y += r1.y;
            }
            if (ROUND_C) {
                v0.x = tf32r(v0.x); v0.y = tf32r(v0.y);
                v1.x = tf32r(v1.x); v1.y = tf32r(v1.y);
            }
            *(float2*)(C + (size_t)gm * ldc + gn) = v0;
            *(float2*)(C + (size_t)(gm + 8) * ldc + gn) = v1;
        }
    }
}

// ---------------- Flash attention ----------------
// grid = (16 q-blocks, 32 bh), 256 threads (8 warps x 16 q-rows).
// Q in registers (scaled by 0.125*log2e, tf32). K/V double-buffered smem.
// Online softmax in base-2. P transposed C->A frag via quad shuffles.
#define KPITCH 68
#define VPITCH 72
#define KTILE  (64 * KPITCH)   // floats per K stage
#define VTILE  (64 * VPITCH)
#define FLASH_SMEM ((2 * KTILE + 2 * VTILE) * 4)

__global__ void __launch_bounds__(256, 1)
flash_kernel(const float* __restrict__ qkv, float* __restrict__ attn) {
    extern __shared__ float sm[];
    float* Ks = sm;                  // [2][KTILE]
    float* Vs = sm + 2 * KTILE;      // [2][VTILE]

    const int by = blockIdx.x;               // q block (128 rows)
    const int z  = blockIdx.y;               // b*16+h
    const int b = z >> 4, h = z & 15;
    const int tid = threadIdx.x, lane = tid & 31, w = tid >> 5;
    const int lr = lane >> 2, lc = lane & 3;

    const float* Qb = qkv + (size_t)b * SEQ * 3 * TOT + h * DH;
    const float* Kb = Qb + TOT;
    const float* Vb = Qb + 2 * TOT;
    const int q0 = by * 128 + w * 16;

    // Q fragments: [ks][4], scaled and re-rounded
    const float sc = 0.18033688011f;   // 0.125 * log2(e)
    uint32_t qf[8][4];
    {
        const float* r0 = Qb + (size_t)(q0 + lr) * 3072;
        const float* r1 = Qb + (size_t)(q0 + lr + 8) * 3072;
        #pragma unroll
        for (int ks = 0; ks < 8; ks++) {
            qf[ks][0] = f2tf32(r0[ks * 8 + lc    ] * sc);
            qf[ks][1] = f2tf32(r1[ks * 8 + lc    ] * sc);
            qf[ks][2] = f2tf32(r0[ks * 8 + lc + 4] * sc);
            qf[ks][3] = f2tf32(r1[ks * 8 + lc + 4] * sc);
        }
    }

    float m0 = -1e30f, m8 = -1e30f, l0 = 0.f, l8 = 0.f;
    float o[8][4];
    #pragma unroll
    for (int nd = 0; nd < 8; nd++)
        #pragma unroll
        for (int r = 0; r < 4; r++) o[nd][r] = 0.f;

    const int nt = 2 * by + 2;   // kv tiles of 64

    auto load_kv = [&](int t) {
        int buf = t & 1;
        uint32_t ku = (uint32_t)__cvta_generic_to_shared(Ks + buf * KTILE);
        uint32_t vu = (uint32_t)__cvta_generic_to_shared(Vs + buf * VTILE);
        int kv0 = t * 64;
        #pragma unroll
        for (int c = tid; c < 1024; c += 256) {
            int r = c >> 4, cc = c & 15;
            cp16(ku + (uint32_t)(r * KPITCH + cc * 4) * 4,
                 Kb + (size_t)(kv0 + r) * 3072 + cc * 4);
            cp16(vu + (uint32_t)(r * VPITCH + cc * 4) * 4,
                 Vb + (size_t)(kv0 + r) * 3072 + cc * 4);
        }
        asm volatile("cp.async.commit_group;");
    };

    load_kv(0);

    for (int t = 0; t < nt; t++) {
        asm volatile("cp.async.wait_group 0;");
        __syncthreads();
        if (t + 1 < nt) load_kv(t + 1);

        const float* ksm = Ks + (t & 1) * KTILE;
        const float* vsm = Vs + (t & 1) * VTILE;

        // ---- S = Qs @ K^T  (16 x 64 per warp) ----
        float s[8][4];
        #pragma unroll
        for (int nj = 0; nj < 8; nj++) {
            float s0 = 0.f, s1 = 0.f, s2 = 0.f, s3 = 0.f;
            #pragma unroll
            for (int ks = 0; ks < 8; ks++) {
                uint32_t b0 = __float_as_uint(ksm[(nj * 8 + lr) * KPITCH + ks * 8 + lc    ]);
                uint32_t b1 = __float_as_uint(ksm[(nj * 8 + lr) * KPITCH + ks * 8 + lc + 4]);
                mma_tf32(s0, s1, s2, s3,
                         qf[ks][0], qf[ks][1], qf[ks][2], qf[ks][3], b0, b1);
            }
            s[nj][0] = s0; s[nj][1] = s1; s[nj][2] = s2; s[nj][3] = s3;
        }

        // ---- causal mask (only last two tiles of this block) ----
        if (t >= 2 * by) {
            const int i0 = q0 + lr, i8 = i0 + 8;
            const int cb = t * 64;
            #pragma unroll
            for (int nj = 0; nj < 8; nj++) {
                int j0 = cb + nj * 8 + 2 * lc;
                if (j0     > i0) s[nj][0] = -1e30f;
                if (j0 + 1 > i0) s[nj][1] = -1e30f;
                if (j0     > i8) s[nj][2] = -1e30f;
                if (j0 + 1 > i8) s[nj][3] = -1e30f;
            }
        }

        // ---- online softmax (base 2) ----
        float mx0 = -1e30f, mx8 = -1e30f;
        #pragma unroll
        for (int nj = 0; nj < 8; nj++) {
            mx0 = fmaxf(mx0, fmaxf(s[nj][0], s[nj][1]));
            mx8 = fmaxf(mx8, fmaxf(s[nj][2], s[nj][3]));
        }
        mx0 = fmaxf(mx0, __shfl_xor_sync(0xffffffffu, mx0, 1));
        mx0 = fmaxf(mx0, __shfl_xor_sync(0xffffffffu, mx0, 2));
        mx8 = fmaxf(mx8, __shfl_xor_sync(0xffffffffu, mx8, 1));
        mx8 = fmaxf(mx8, __shfl_xor_sync(0xffffffffu, mx8, 2));

        float mn0 = fmaxf(m0, mx0), mn8 = fmaxf(m8, mx8);
        float es0 = ex2(m0 - mn0), es8 = ex2(m8 - mn8);
        m0 = mn0; m8 = mn8;

        float sum0 = 0.f, sum8 = 0.f;
        #pragma unroll
        for (int nj = 0; nj < 8; nj++) {
            s[nj][0] = ex2(s[nj][0] - mn0);
            s[nj][1] = ex2(s[nj][1] - mn0);
            s[nj][2] = ex2(s[nj][2] - mn8);
            s[nj][3] = ex2(s[nj][3] - mn8);
            sum0 += s[nj][0] + s[nj][1];
            sum8 += s[nj][2] + s[nj][3];
        }
        sum0 += __shfl_xor_sync(0xffffffffu, sum0, 1);
        sum0 += __shfl_xor_sync(0xffffffffu, sum0, 2);
        sum8 += __shfl_xor_sync(0xffffffffu, sum8, 1);
        sum8 += __shfl_xor_sync(0xffffffffu, sum8, 2);
        l0 = l0 * es0 + sum0;
        l8 = l8 * es8 + sum8;

        #pragma unroll
        for (int nd = 0; nd < 8; nd++) {
            o[nd][0] *= es0; o[nd][1] *= es0;
            o[nd][2] *= es8; o[nd][3] *= es8;
        }

        // ---- O += P @ V : transpose P C-frag -> A-frag via quad shuffles ----
        const int qb = lane & ~3;
        const int sA = qb | (lc >> 1);
        const int sB = qb | ((lc >> 1) + 2);
        const bool odd = lc & 1;
        #pragma unroll
        for (int kc = 0; kc < 8; kc++) {
            float e00 = __shfl_sync(0xffffffffu, s[kc][0], sA);
            float e10 = __shfl_sync(0xffffffffu, s[kc][1], sA);
            float e01 = __shfl_sync(0xffffffffu, s[kc][0], sB);
            float e11 = __shfl_sync(0xffffffffu, s[kc][1], sB);
            float e20 = __shfl_sync(0xffffffffu, s[kc][2], sA);
            float e30 = __shfl_sync(0xffffffffu, s[kc][3], sA);
            float e21 = __shfl_sync(0xffffffffu, s[kc][2], sB);
            float e31 = __shfl_sync(0xffffffffu, s[kc][3], sB);
            uint32_t a0 = f2tf32(odd ? e10 : e00);
            uint32_t a2 = f2tf32(odd ? e11 : e01);
            uint32_t a1 = f2tf32(odd ? e30 : e20);
            uint32_t a3 = f2tf32(odd ? e31 : e21);
            #pragma unroll
            for (int nd = 0; nd < 8; nd++) {
                uint32_t b0 = __float_as_uint(vsm[(kc * 8 + lc    ) * VPITCH + nd * 8 + lr]);
                uint32_t b1 = __float_as_uint(vsm[(kc * 8 + lc + 4) * VPITCH + nd * 8 + lr]);
                mma_tf32(o[nd][0], o[nd][1], o[nd][2], o[nd][3], a0, a1, a2, a3, b0, b1);
            }
        }
        __syncthreads();
    }

    // ---- epilogue: O /= l, round, store ----
    const float inv0 = 1.f / l0, inv8 = 1.f / l8;
    const size_t trow = (size_t)b * SEQ + q0;
    float* ob0 = attn + (trow + lr    ) * TOT + h * DH;
    float* ob8 = attn + (trow + lr + 8) * TOT + h * DH;
    #pragma unroll
    for (int nd = 0; nd < 8; nd++) {
        int col = nd * 8 + 2 * lc;
        ob0[col    ] = tf32r(o[nd][0] * inv0);
        ob0[col + 1] = tf32r(o[nd][1] * inv0);
        ob8[col    ] = tf32r(o[nd][2] * inv8);
        ob8[col + 1] = tf32r(o[nd][3] * inv8);
    }
}

// ---------------- launch ----------------
extern "C" void kernel_launch(void* const* d_in, const int* in_sizes, int n_in,
                              void* d_out, int out_size) {
    const float* x      = (const float*)d_in[0];
    const float* w_ln1  = (const float*)d_in[1];
    const float* w_qkv  = (const float*)d_in[2];
    const float* w_out  = (const float*)d_in[3];
    const float* w_ln2  = (const float*)d_in[4];
    const float* w_gate = (const float*)d_in[5];
    const float* w_up   = (const float*)d_in[6];
    const float* w_down = (const float*)d_in[7];
    float* out = (float*)d_out;

    void* p;
    cudaGetSymbolAddress(&p, g_h);    float* h    = (float*)p;
    cudaGetSymbolAddress(&p, g_qkv);  float* qkv  = (float*)p;
    cudaGetSymbolAddress(&p, g_attn); float* attn = (float*)p;
    cudaGetSymbolAddress(&p, g_x2);   float* x2   = (float*)p;
    cudaGetSymbolAddress(&p, g_gate); float* gate = (float*)p;
    cudaGetSymbolAddress(&p, g_up);   float* up   = (float*)p;
    cudaGetSymbolAddress(&p, g_wc);   float* wc   = (float*)p;

    float* wqkv_c  = wc;                      // 3M floats
    float* wout_c  = wqkv_c + 3*1024*1024;    // 1M
    float* wgate_c = wout_c + 1024*1024;      // 4M
    float* wup_c   = wgate_c + 4*1024*1024;   // 4M
    float* wdown_c = wup_c + 4*1024*1024;     // 4M

    // opt-in dynamic smem (idempotent)
    constexpr int GEMM_SMEM = 3 * 2 * 128 * 20 * 4;   // 61440
    cudaFuncSetAttribute(mma_gemm3<false,true>,  cudaFuncAttributeMaxDynamicSharedMemorySize, GEMM_SMEM);
    cudaFuncSetAttribute(mma_gemm3<false,false>, cudaFuncAttributeMaxDynamicSharedMemorySize, GEMM_SMEM);
    cudaFuncSetAttribute(mma_gemm3<true,false>,  cudaFuncAttributeMaxDynamicSharedMemorySize, GEMM_SMEM);
    cudaFuncSetAttribute(flash_kernel, cudaFuncAttributeMaxDynamicSharedMemorySize, FLASH_SMEM);

    // 0) round weights to tf32
    round_tf32_kernel<<<512, 256>>>(w_qkv,  wqkv_c,  3*1024*1024/4);
    round_tf32_kernel<<<512, 256>>>(w_out,  wout_c,  1024*1024/4);
    round_tf32_kernel<<<512, 256>>>(w_gate, wgate_c, 4*1024*1024/4);
    round_tf32_kernel<<<512, 256>>>(w_up,   wup_c,   4*1024*1024/4);
    round_tf32_kernel<<<512, 256>>>(w_down, wdown_c, 4*1024*1024/4);

    // 1) h = rmsnorm(x, w_ln1) [rounded]
    rmsnorm_kernel<<<NTOK, 256>>>(x, w_ln1, h);

    // 2) qkv = h @ w_qkv^T [rounded]
    mma_gemm3<false,true><<<dim3(3*TOT/128, NTOK/128), 256, GEMM_SMEM>>>(
        h, D_MODEL, wqkv_c, D_MODEL, qkv, 3*TOT, nullptr, D_MODEL);

    // 3) RoPE [rounded]
    rope_kernel<<<NTOK, 512>>>(qkv);

    // 4) flash attention -> attn [rounded]
    flash_kernel<<<dim3(SEQ/128, BATCH*NH), 256, FLASH_SMEM>>>(qkv, attn);

    // 5) x2 = x + attn @ w_out^T
    mma_gemm3<true,false><<<dim3(D_MODEL/128, NTOK/128), 256, GEMM_SMEM>>>(
        attn, TOT, wout_c, TOT, x2, D_MODEL, x, TOT);

    // 6) h = rmsnorm(x2, w_ln2) [rounded]
    rmsnorm_kernel<<<NTOK, 256>>>(x2, w_ln2, h);

    // 7) gate/up projections
    mma_gemm3<false,false><<<dim3(D_FF/128, NTOK/128), 256, GEMM_SMEM>>>(
        h, D_MODEL, wgate_c, D_MODEL, gate, D_FF, nullptr, D_MODEL);
    mma_gemm3<false,false><<<dim3(D_FF/128, NTOK/128), 256, GEMM_SMEM>>>(
        h, D_MODEL, wup_c, D_MODEL, up, D_FF, nullptr, D_MODEL);

    // 8) gate = silu(gate) * up [rounded]
    swiglu_kernel<<<4096, 256>>>(gate, up, NTOK * D_FF / 4);

    // 9) out = x2 + gate @ w_down^T
    mma_gemm3<true,false><<<dim3(D_MODEL/128, NTOK/128), 256, GEMM_SMEM>>>(
        gate, D_FF, wdown_c, D_FF, out, D_MODEL, x2, D_FF);
}

// round 9
// speedup vs baseline: 4.0586x; 1.0993x over previous
#include <cuda_runtime.h>
#include <math.h>
#include <stdint.h>

// ---------------- problem constants ----------------
#define D_MODEL 1024
#define D_FF    4096
#define NH      16
#define DH      64
#define TOT     1024
#define BATCH   2
#define SEQ     2048
#define NTOK    (BATCH*SEQ)

// ---------------- scratch ----------------
__device__ float g_h   [(size_t)NTOK * D_MODEL];
__device__ float g_qkv [(size_t)NTOK * 3 * TOT];
__device__ float g_attn[(size_t)NTOK * TOT];
__device__ float g_x2  [(size_t)NTOK * D_MODEL];
__device__ float g_gate[(size_t)NTOK * D_FF];
__device__ float g_up  [(size_t)NTOK * D_FF];
__device__ float g_wc  [(size_t)16 * 1024 * 1024];   // tf32-rounded weights

// ---------------- helpers ----------------
__device__ __forceinline__ void cp16(uint32_t dst, const void* src) {
    asm volatile("cp.async.cg.shared.global [%0], [%1], 16;" :: "r"(dst), "l"(src));
}
__device__ __forceinline__ uint32_t f2tf32(float f) {
    uint32_t r;
    asm("cvt.rna.tf32.f32 %0, %1;" : "=r"(r) : "f"(f));
    return r;
}
__device__ __forceinline__ float tf32r(float f) { return __uint_as_float(f2tf32(f)); }
__device__ __forceinline__ float ex2(float x) {
    float r;
    asm("ex2.approx.ftz.f32 %0, %1;" : "=f"(r) : "f"(x));
    return r;
}
__device__ __forceinline__ void mma_tf32(float& c0, float& c1, float& c2, float& c3,
                                         uint32_t a0, uint32_t a1, uint32_t a2, uint32_t a3,
                                         uint32_t b0, uint32_t b1) {
    asm volatile(
        "mma.sync.aligned.m16n8k8.row.col.f32.tf32.tf32.f32 "
        "{%0,%1,%2,%3}, {%4,%5,%6,%7}, {%8,%9}, {%0,%1,%2,%3};"
        : "+f"(c0), "+f"(c1), "+f"(c2), "+f"(c3)
        : "r"(a0), "r"(a1), "r"(a2), "r"(a3), "r"(b0), "r"(b1));
}

// ---------------- block reduction ----------------
__device__ __forceinline__ float block_reduce_sum(float v) {
    __shared__ float sh[33];
    int lane = threadIdx.x & 31, wid = threadIdx.x >> 5;
    #pragma unroll
    for (int o = 16; o; o >>= 1) v += __shfl_xor_sync(0xffffffffu, v, o);
    if (lane == 0) sh[wid] = v;
    __syncthreads();
    if (wid == 0) {
        v = (lane < (blockDim.x >> 5)) ? sh[lane] : 0.f;
        #pragma unroll
        for (int o = 16; o; o >>= 1) v += __shfl_xor_sync(0xffffffffu, v, o);
        if (lane == 0) sh[32] = v;
    }
    __syncthreads();
    float r = sh[32];
    __syncthreads();
    return r;
}

// ---------------- tf32 rounding pass (weights) ----------------
__global__ void round_tf32_kernel(const float* __restrict__ in, float* __restrict__ out, int n4) {
    int idx = blockIdx.x * blockDim.x + threadIdx.x;
    int stride = gridDim.x * blockDim.x;
    for (; idx < n4; idx += stride) {
        float4 v = ((const float4*)in)[idx];
        v.x = tf32r(v.x); v.y = tf32r(v.y); v.z = tf32r(v.z); v.w = tf32r(v.w);
        ((float4*)out)[idx] = v;
    }
}

// ---------------- RMSNorm (rounded output feeds GEMMs) ----------------
__global__ void rmsnorm_kernel(const float* __restrict__ x,
                               const float* __restrict__ w,
                               float* __restrict__ o) {
    const size_t base = (size_t)blockIdx.x * D_MODEL;
    float ss = 0.f;
    for (int i = threadIdx.x; i < D_MODEL; i += 256) {
        float v = x[base + i];
        ss += v * v;
    }
    ss = block_reduce_sum(ss);
    float r = rsqrtf(ss * (1.0f / D_MODEL) + 1e-6f);
    for (int i = threadIdx.x; i < D_MODEL; i += 256)
        o[base + i] = tf32r(x[base + i] * r * w[i]);
}

// ---------------- RoPE (rounded q,k) ----------------
__global__ void rope_kernel(float* __restrict__ qkv) {
    const int t   = blockIdx.x;
    const int pos = t & (SEQ - 1);
    const int h   = threadIdx.x >> 5;
    const int i   = threadIdx.x & 31;
    float invf = expf(-(2.0f * (float)i / (float)DH) * logf(10000.0f));
    float fr = (float)pos * invf;
    float s, c;
    sincosf(fr, &s, &c);
    float* q = qkv + (size_t)t * (3 * TOT) + h * DH;
    float q1 = q[i], q2 = q[i + 32];
    q[i]      = tf32r(q1 * c - q2 * s);
    q[i + 32] = tf32r(q2 * c + q1 * s);
    float* k = q + TOT;
    float k1 = k[i], k2 = k[i + 32];
    k[i]      = tf32r(k1 * c - k2 * s);
    k[i + 32] = tf32r(k2 * c + k1 * s);
}

// ---------------- TF32 mma.sync GEMM, BK=32, 3-stage ----------------
// C[M,N] = A[M,K] @ B[N,K]^T, epilogue variants:
//   EPI 0: plain store        EPI 1: tf32-round store
//   EPI 2: += X residual      EPI 3: tf32r(silu(X) * acc)  (fused SwiGLU)
#define EPI_PLAIN  0
#define EPI_ROUND  1
#define EPI_RES    2
#define EPI_SWIGLU 3

#define GPITCH 36
#define GSTAGE (128 * GPITCH)                 // floats per matrix per stage
#define GEMM_SMEM (6 * GSTAGE * 4)            // 3 stages x (A+B) = 108 KB

template<int EPI>
__global__ void __launch_bounds__(256, 2)
gemm_tf32(const float* __restrict__ A, int lda,
          const float* __restrict__ B, int ldb,
          float* __restrict__ C, int ldc,
          const float* __restrict__ X, int K) {
    extern __shared__ float smg[];
    float* As = smg;                    // [3][GSTAGE]
    float* Bs = smg + 3 * GSTAGE;       // [3][GSTAGE]

    const int tid  = threadIdx.x;
    const int lane = tid & 31;
    const int wid  = tid >> 5;
    const int wm_base = (wid >> 2) * 64;    // 2 M-warps x 4 N-warps
    const int wn_base = (wid & 3) * 32;
    const int m0 = blockIdx.y * 128, n0 = blockIdx.x * 128;
    const int lr = lane >> 2, lc = lane & 3;

    float acc[4][4][4];
    #pragma unroll
    for (int i = 0; i < 4; i++)
        #pragma unroll
        for (int j = 0; j < 4; j++)
            #pragma unroll
            for (int r = 0; r < 4; r++) acc[i][j][r] = 0.f;

    const int nt = K / 32;

    auto load_tile = [&](int stg, int kt) {
        uint32_t as_u = (uint32_t)__cvta_generic_to_shared(As + stg * GSTAGE);
        uint32_t bs_u = (uint32_t)__cvta_generic_to_shared(Bs + stg * GSTAGE);
        #pragma unroll
        for (int i = 0; i < 4; i++) {          // 128 rows x 8 16B-chunks / 256 thr
            int c = tid + i * 256, row = c >> 3, sub = c & 7;
            uint32_t so = (uint32_t)(row * GPITCH + sub * 4) * 4;
            cp16(as_u + so, A + (size_t)(m0 + row) * lda + kt + sub * 4);
            cp16(bs_u + so, B + (size_t)(n0 + row) * ldb + kt + sub * 4);
        }
        asm volatile("cp.async.commit_group;");
    };

    load_tile(0, 0);
    if (nt > 1) load_tile(1, 32);

    for (int t = 0; t < nt; t++) {
        if (t + 1 < nt) asm volatile("cp.async.wait_group 1;");
        else            asm volatile("cp.async.wait_group 0;");
        __syncthreads();
        // stage (t+2)%3 was last read in compute t-1 (all threads passed the
        // sync above after that compute) -> safe to overwrite now.
        if (t + 2 < nt) load_tile((t + 2) % 3, (t + 2) * 32);

        const float* as = As + (t % 3) * GSTAGE;
        const float* bs = Bs + (t % 3) * GSTAGE;
        #pragma unroll
        for (int ks = 0; ks < 4; ks++) {
            const int k0 = ks * 8;
            uint32_t af[4][4];
            uint32_t bf[4][2];
            #pragma unroll
            for (int mi = 0; mi < 4; mi++) {
                int mr = wm_base + mi * 16 + lr;
                af[mi][0] = __float_as_uint(as[(mr    ) * GPITCH + k0 + lc    ]);
                af[mi][1] = __float_as_uint(as[(mr + 8) * GPITCH + k0 + lc    ]);
                af[mi][2] = __float_as_uint(as[(mr    ) * GPITCH + k0 + lc + 4]);
                af[mi][3] = __float_as_uint(as[(mr + 8) * GPITCH + k0 + lc + 4]);
            }
            #pragma unroll
            for (int nj = 0; nj < 4; nj++) {
                int nr = wn_base + nj * 8 + lr;
                bf[nj][0] = __float_as_uint(bs[nr * GPITCH + k0 + lc    ]);
                bf[nj][1] = __float_as_uint(bs[nr * GPITCH + k0 + lc + 4]);
            }
            #pragma unroll
            for (int mi = 0; mi < 4; mi++)
                #pragma unroll
                for (int nj = 0; nj < 4; nj++)
                    mma_tf32(acc[mi][nj][0], acc[mi][nj][1], acc[mi][nj][2], acc[mi][nj][3],
                             af[mi][0], af[mi][1], af[mi][2], af[mi][3],
                             bf[nj][0], bf[nj][1]);
        }
        __syncthreads();   // before next iter's load overwrites stage (t+3)%3 == t%3
    }

    #pragma unroll
    for (int mi = 0; mi < 4; mi++) {
        int gm = m0 + wm_base + mi * 16 + lr;
        #pragma unroll
        for (int nj = 0; nj < 4; nj++) {
            int gn = n0 + wn_base + nj * 8 + 2 * lc;
            float2 v0 = make_float2(acc[mi][nj][0], acc[mi][nj][1]);
            float2 v1 = make_float2(acc[mi][nj][2], acc[mi][nj][3]);
            if (EPI == EPI_RES) {
                float2 r0 = *(const float2*)(X + (size_t)gm * ldc + gn);
                float2 r1 = *(const float2*)(X + (size_t)(gm + 8) * ldc + gn);
                v0.x += r0.x; v0.y += r0.y;
                v1.x += r1.x; v1.y += r1.y;
            }
            if (EPI == EPI_SWIGLU) {
                float2 g0 = *(const float2*)(X + (size_t)gm * ldc + gn);
                float2 g1 = *(const float2*)(X + (size_t)(gm + 8) * ldc + gn);
                v0.x = tf32r(g0.x / (1.f + __expf(-g0.x)) * v0.x);
                v0.y = tf32r(g0.y / (1.f + __expf(-g0.y)) * v0.y);
                v1.x = tf32r(g1.x / (1.f + __expf(-g1.x)) * v1.x);
                v1.y = tf32r(g1.y / (1.f + __expf(-g1.y)) * v1.y);
            }
            if (EPI == EPI_ROUND) {
                v0.x = tf32r(v0.x); v0.y = tf32r(v0.y);
                v1.x = tf32r(v1.x); v1.y = tf32r(v1.y);
            }
            *(float2*)(C + (size_t)gm * ldc + gn) = v0;
            *(float2*)(C + (size_t)(gm + 8) * ldc + gn) = v1;
        }
    }
}

// ---------------- Flash attention (unchanged from R5, known-good) ----------------
#define KPITCH 68
#define VPITCH 72
#define KTILE  (64 * KPITCH)
#define VTILE  (64 * VPITCH)
#define FLASH_SMEM ((2 * KTILE + 2 * VTILE) * 4)

__global__ void __launch_bounds__(256, 1)
flash_kernel(const float* __restrict__ qkv, float* __restrict__ attn) {
    extern __shared__ float sm[];
    float* Ks = sm;
    float* Vs = sm + 2 * KTILE;

    const int by = blockIdx.x;
    const int z  = blockIdx.y;
    const int b = z >> 4, h = z & 15;
    const int tid = threadIdx.x, lane = tid & 31, w = tid >> 5;
    const int lr = lane >> 2, lc = lane & 3;

    const float* Qb = qkv + (size_t)b * SEQ * 3 * TOT + h * DH;
    const float* Kb = Qb + TOT;
    const float* Vb = Qb + 2 * TOT;
    const int q0 = by * 128 + w * 16;

    const float sc = 0.18033688011f;   // 0.125 * log2(e)
    uint32_t qf[8][4];
    {
        const float* r0 = Qb + (size_t)(q0 + lr) * 3072;
        const float* r1 = Qb + (size_t)(q0 + lr + 8) * 3072;
        #pragma unroll
        for (int ks = 0; ks < 8; ks++) {
            qf[ks][0] = f2tf32(r0[ks * 8 + lc    ] * sc);
            qf[ks][1] = f2tf32(r1[ks * 8 + lc    ] * sc);
            qf[ks][2] = f2tf32(r0[ks * 8 + lc + 4] * sc);
            qf[ks][3] = f2tf32(r1[ks * 8 + lc + 4] * sc);
        }
    }

    float m0 = -1e30f, m8 = -1e30f, l0 = 0.f, l8 = 0.f;
    float o[8][4];
    #pragma unroll
    for (int nd = 0; nd < 8; nd++)
        #pragma unroll
        for (int r = 0; r < 4; r++) o[nd][r] = 0.f;

    const int nt = 2 * by + 2;

    auto load_kv = [&](int t) {
        int buf = t & 1;
        uint32_t ku = (uint32_t)__cvta_generic_to_shared(Ks + buf * KTILE);
        uint32_t vu = (uint32_t)__cvta_generic_to_shared(Vs + buf * VTILE);
        int kv0 = t * 64;
        #pragma unroll
        for (int c = tid; c < 1024; c += 256) {
            int r = c >> 4, cc = c & 15;
            cp16(ku + (uint32_t)(r * KPITCH + cc * 4) * 4,
                 Kb + (size_t)(kv0 + r) * 3072 + cc * 4);
            cp16(vu + (uint32_t)(r * VPITCH + cc * 4) * 4,
                 Vb + (size_t)(kv0 + r) * 3072 + cc * 4);
        }
        asm volatile("cp.async.commit_group;");
    };

    load_kv(0);

    for (int t = 0; t < nt; t++) {
        asm volatile("cp.async.wait_group 0;");
        __syncthreads();
        if (t + 1 < nt) load_kv(t + 1);

        const float* ksm = Ks + (t & 1) * KTILE;
        const float* vsm = Vs + (t & 1) * VTILE;

        float s[8][4];
        #pragma unroll
        for (int nj = 0; nj < 8; nj++) {
            float s0 = 0.f, s1 = 0.f, s2 = 0.f, s3 = 0.f;
            #pragma unroll
            for (int ks = 0; ks < 8; ks++) {
                uint32_t b0 = __float_as_uint(ksm[(nj * 8 + lr) * KPITCH + ks * 8 + lc    ]);
                uint32_t b1 = __float_as_uint(ksm[(nj * 8 + lr) * KPITCH + ks * 8 + lc + 4]);
                mma_tf32(s0, s1, s2, s3,
                         qf[ks][0], qf[ks][1], qf[ks][2], qf[ks][3], b0, b1);
            }
            s[nj][0] = s0; s[nj][1] = s1; s[nj][2] = s2; s[nj][3] = s3;
        }

        if (t >= 2 * by) {
            const int i0 = q0 + lr, i8 = i0 + 8;
            const int cb = t * 64;
            #pragma unroll
            for (int nj = 0; nj < 8; nj++) {
                int j0 = cb + nj * 8 + 2 * lc;
                if (j0     > i0) s[nj][0] = -1e30f;
                if (j0 + 1 > i0) s[nj][1] = -1e30f;
                if (j0     > i8) s[nj][2] = -1e30f;
                if (j0 + 1 > i8) s[nj][3] = -1e30f;
            }
        }

        float mx0 = -1e30f, mx8 = -1e30f;
        #pragma unroll
        for (int nj = 0; nj < 8; nj++) {
            mx0 = fmaxf(mx0, fmaxf(s[nj][0], s[nj][1]));
            mx8 = fmaxf(mx8, fmaxf(s[nj][2], s[nj][3]));
        }
        mx0 = fmaxf(mx0, __shfl_xor_sync(0xffffffffu, mx0, 1));
        mx0 = fmaxf(mx0, __shfl_xor_sync(0xffffffffu, mx0, 2));
        mx8 = fmaxf(mx8, __shfl_xor_sync(0xffffffffu, mx8, 1));
        mx8 = fmaxf(mx8, __shfl_xor_sync(0xffffffffu, mx8, 2));

        float mn0 = fmaxf(m0, mx0), mn8 = fmaxf(m8, mx8);
        float es0 = ex2(m0 - mn0), es8 = ex2(m8 - mn8);
        m0 = mn0; m8 = mn8;

        float sum0 = 0.f, sum8 = 0.f;
        #pragma unroll
        for (int nj = 0; nj < 8; nj++) {
            s[nj][0] = ex2(s[nj][0] - mn0);
            s[nj][1] = ex2(s[nj][1] - mn0);
            s[nj][2] = ex2(s[nj][2] - mn8);
            s[nj][3] = ex2(s[nj][3] - mn8);
            sum0 += s[nj][0] + s[nj][1];
            sum8 += s[nj][2] + s[nj][3];
        }
        sum0 += __shfl_xor_sync(0xffffffffu, sum0, 1);
        sum0 += __shfl_xor_sync(0xffffffffu, sum0, 2);
        sum8 += __shfl_xor_sync(0xffffffffu, sum8, 1);
        sum8 += __shfl_xor_sync(0xffffffffu, sum8, 2);
        l0 = l0 * es0 + sum0;
        l8 = l8 * es8 + sum8;

        #pragma unroll
        for (int nd = 0; nd < 8; nd++) {
            o[nd][0] *= es0; o[nd][1] *= es0;
            o[nd][2] *= es8; o[nd][3] *= es8;
        }

        const int qb = lane & ~3;
        const int sA = qb | (lc >> 1);
        const int sB = qb | ((lc >> 1) + 2);
        const bool odd = lc & 1;
        #pragma unroll
        for (int kc = 0; kc < 8; kc++) {
            float e00 = __shfl_sync(0xffffffffu, s[kc][0], sA);
            float e10 = __shfl_sync(0xffffffffu, s[kc][1], sA);
            float e01 = __shfl_sync(0xffffffffu, s[kc][0], sB);
            float e11 = __shfl_sync(0xffffffffu, s[kc][1], sB);
            float e20 = __shfl_sync(0xffffffffu, s[kc][2], sA);
            float e30 = __shfl_sync(0xffffffffu, s[kc][3], sA);
            float e21 = __shfl_sync(0xffffffffu, s[kc][2], sB);
            float e31 = __shfl_sync(0xffffffffu, s[kc][3], sB);
            uint32_t a0 = f2tf32(odd ? e10 : e00);
            uint32_t a2 = f2tf32(odd ? e11 : e01);
            uint32_t a1 = f2tf32(odd ? e30 : e20);
            uint32_t a3 = f2tf32(odd ? e31 : e21);
            #pragma unroll
            for (int nd = 0; nd < 8; nd++) {
                uint32_t b0 = __float_as_uint(vsm[(kc * 8 + lc    ) * VPITCH + nd * 8 + lr]);
                uint32_t b1 = __float_as_uint(vsm[(kc * 8 + lc + 4) * VPITCH + nd * 8 + lr]);
                mma_tf32(o[nd][0], o[nd][1], o[nd][2], o[nd][3], a0, a1, a2, a3, b0, b1);
            }
        }
        __syncthreads();
    }

    const float inv0 = 1.f / l0, inv8 = 1.f / l8;
    const size_t trow = (size_t)b * SEQ + q0;
    float* ob0 = attn + (trow + lr    ) * TOT + h * DH;
    float* ob8 = attn + (trow + lr + 8) * TOT + h * DH;
    #pragma unroll
    for (int nd = 0; nd < 8; nd++) {
        int col = nd * 8 + 2 * lc;
        ob0[col    ] = tf32r(o[nd][0] * inv0);
        ob0[col + 1] = tf32r(o[nd][1] * inv0);
        ob8[col    ] = tf32r(o[nd][2] * inv8);
        ob8[col + 1] = tf32r(o[nd][3] * inv8);
    }
}

// ---------------- launch ----------------
extern "C" void kernel_launch(void* const* d_in, const int* in_sizes, int n_in,
                              void* d_out, int out_size) {
    const float* x      = (const float*)d_in[0];
    const float* w_ln1  = (const float*)d_in[1];
    const float* w_qkv  = (const float*)d_in[2];
    const float* w_out  = (const float*)d_in[3];
    const float* w_ln2  = (const float*)d_in[4];
    const float* w_gate = (const float*)d_in[5];
    const float* w_up   = (const float*)d_in[6];
    const float* w_down = (const float*)d_in[7];
    float* out = (float*)d_out;

    void* p;
    cudaGetSymbolAddress(&p, g_h);    float* h    = (float*)p;
    cudaGetSymbolAddress(&p, g_qkv);  float* qkv  = (float*)p;
    cudaGetSymbolAddress(&p, g_attn); float* attn = (float*)p;
    cudaGetSymbolAddress(&p, g_x2);   float* x2   = (float*)p;
    cudaGetSymbolAddress(&p, g_gate); float* gate = (float*)p;
    cudaGetSymbolAddress(&p, g_up);   float* up   = (float*)p;
    cudaGetSymbolAddress(&p, g_wc);   float* wc   = (float*)p;

    float* wqkv_c  = wc;
    float* wout_c  = wqkv_c + 3*1024*1024;
    float* wgate_c = wout_c + 1024*1024;
    float* wup_c   = wgate_c + 4*1024*1024;
    float* wdown_c = wup_c + 4*1024*1024;

    cudaFuncSetAttribute(gemm_tf32<EPI_PLAIN>,  cudaFuncAttributeMaxDynamicSharedMemorySize, GEMM_SMEM);
    cudaFuncSetAttribute(gemm_tf32<EPI_ROUND>,  cudaFuncAttributeMaxDynamicSharedMemorySize, GEMM_SMEM);
    cudaFuncSetAttribute(gemm_tf32<EPI_RES>,    cudaFuncAttributeMaxDynamicSharedMemorySize, GEMM_SMEM);
    cudaFuncSetAttribute(gemm_tf32<EPI_SWIGLU>, cudaFuncAttributeMaxDynamicSharedMemorySize, GEMM_SMEM);
    cudaFuncSetAttribute(flash_kernel, cudaFuncAttributeMaxDynamicSharedMemorySize, FLASH_SMEM);

    // 0) round weights to tf32
    round_tf32_kernel<<<512, 256>>>(w_qkv,  wqkv_c,  3*1024*1024/4);
    round_tf32_kernel<<<512, 256>>>(w_out,  wout_c,  1024*1024/4);
    round_tf32_kernel<<<512, 256>>>(w_gate, wgate_c, 4*1024*1024/4);
    round_tf32_kernel<<<512, 256>>>(w_up,   wup_c,   4*1024*1024/4);
    round_tf32_kernel<<<512, 256>>>(w_down, wdown_c, 4*1024*1024/4);

    // 1) h = rmsnorm(x, w_ln1) [rounded]
    rmsnorm_kernel<<<NTOK, 256>>>(x, w_ln1, h);

    // 2) qkv = h @ w_qkv^T [rounded]
    gemm_tf32<EPI_ROUND><<<dim3(3*TOT/128, NTOK/128), 256, GEMM_SMEM>>>(
        h, D_MODEL, wqkv_c, D_MODEL, qkv, 3*TOT, nullptr, D_MODEL);

    // 3) RoPE [rounded]
    rope_kernel<<<NTOK, 512>>>(qkv);

    // 4) flash attention -> attn [rounded]
    flash_kernel<<<dim3(SEQ/128, BATCH*NH), 256, FLASH_SMEM>>>(qkv, attn);

    // 5) x2 = x + attn @ w_out^T
    gemm_tf32<EPI_RES><<<dim3(D_MODEL/128, NTOK/128), 256, GEMM_SMEM>>>(
        attn, TOT, wout_c, TOT, x2, D_MODEL, x, TOT);

    // 6) h = rmsnorm(x2, w_ln2) [rounded]
    rmsnorm_kernel<<<NTOK, 256>>>(x2, w_ln2, h);

    // 7) gate = h @ w_gate^T (raw); then up-proj with fused SwiGLU epilogue:
    //    gate <- tf32r(silu(gate) * (h @ w_up^T))
    gemm_tf32<EPI_PLAIN><<<dim3(D_FF/128, NTOK/128), 256, GEMM_SMEM>>>(
        h, D_MODEL, wgate_c, D_MODEL, gate, D_FF, nullptr, D_MODEL);
    gemm_tf32<EPI_SWIGLU><<<dim3(D_FF/128, NTOK/128), 256, GEMM_SMEM>>>(
        h, D_MODEL, wup_c, D_MODEL, gate, D_FF, gate, D_MODEL);

    // 8) out = x2 + gate @ w_down^T
    gemm_tf32<EPI_RES><<<dim3(D_MODEL/128, NTOK/128), 256, GEMM_SMEM>>>(
        gate, D_FF, wdown_c, D_FF, out, D_MODEL, x2, D_FF);
}

// round 10
// speedup vs baseline: 6.6762x; 1.6450x over previous
#include <cuda_runtime.h>
#include <cuda_fp16.h>
#include <math.h>
#include <stdint.h>

// ---------------- problem constants ----------------
#define D_MODEL 1024
#define D_FF    4096
#define NH      16
#define DH      64
#define TOT     1024
#define BATCH   2
#define SEQ     2048
#define NTOK    (BATCH*SEQ)

// ---------------- scratch ----------------
__device__ __half g_hh  [(size_t)NTOK * D_MODEL];        // rmsnorm out (fp16)
__device__ float  g_qkv [(size_t)NTOK * 3 * TOT];        // qkv (fp32, tf32-rounded for flash)
__device__ __half g_attnh[(size_t)NTOK * TOT];           // flash out (fp16)
__device__ float  g_x2  [(size_t)NTOK * D_MODEL];        // residual 2 (fp32)
__device__ float  g_gate[(size_t)NTOK * D_FF];           // gate raw (fp32)
__device__ __half g_ffh [(size_t)NTOK * D_FF];           // swiglu out (fp16)
__device__ __half g_wh  [(size_t)16 * 1024 * 1024];      // fp16 weights

// ---------------- helpers ----------------
__device__ __forceinline__ void cp16(uint32_t dst, const void* src) {
    asm volatile("cp.async.cg.shared.global [%0], [%1], 16;" :: "r"(dst), "l"(src));
}
__device__ __forceinline__ uint32_t f2tf32(float f) {
    uint32_t r;
    asm("cvt.rna.tf32.f32 %0, %1;" : "=r"(r) : "f"(f));
    return r;
}
__device__ __forceinline__ float tf32r(float f) { return __uint_as_float(f2tf32(f)); }
__device__ __forceinline__ float ex2(float x) {
    float r;
    asm("ex2.approx.ftz.f32 %0, %1;" : "=f"(r) : "f"(x));
    return r;
}
__device__ __forceinline__ void mma_tf32(float& c0, float& c1, float& c2, float& c3,
                                         uint32_t a0, uint32_t a1, uint32_t a2, uint32_t a3,
                                         uint32_t b0, uint32_t b1) {
    asm volatile(
        "mma.sync.aligned.m16n8k8.row.col.f32.tf32.tf32.f32 "
        "{%0,%1,%2,%3}, {%4,%5,%6,%7}, {%8,%9}, {%0,%1,%2,%3};"
        : "+f"(c0), "+f"(c1), "+f"(c2), "+f"(c3)
        : "r"(a0), "r"(a1), "r"(a2), "r"(a3), "r"(b0), "r"(b1));
}
__device__ __forceinline__ void mma_f16(float& c0, float& c1, float& c2, float& c3,
                                        uint32_t a0, uint32_t a1, uint32_t a2, uint32_t a3,
                                        uint32_t b0, uint32_t b1) {
    asm volatile(
        "mma.sync.aligned.m16n8k16.row.col.f32.f16.f16.f32 "
        "{%0,%1,%2,%3}, {%4,%5,%6,%7}, {%8,%9}, {%0,%1,%2,%3};"
        : "+f"(c0), "+f"(c1), "+f"(c2), "+f"(c3)
        : "r"(a0), "r"(a1), "r"(a2), "r"(a3), "r"(b0), "r"(b1));
}

// ---------------- block reduction ----------------
__device__ __forceinline__ float block_reduce_sum(float v) {
    __shared__ float sh[33];
    int lane = threadIdx.x & 31, wid = threadIdx.x >> 5;
    #pragma unroll
    for (int o = 16; o; o >>= 1) v += __shfl_xor_sync(0xffffffffu, v, o);
    if (lane == 0) sh[wid] = v;
    __syncthreads();
    if (wid == 0) {
        v = (lane < (blockDim.x >> 5)) ? sh[lane] : 0.f;
        #pragma unroll
        for (int o = 16; o; o >>= 1) v += __shfl_xor_sync(0xffffffffu, v, o);
        if (lane == 0) sh[32] = v;
    }
    __syncthreads();
    float r = sh[32];
    __syncthreads();
    return r;
}

// ---------------- weights fp32 -> fp16 ----------------
__global__ void to_half_kernel(const float* __restrict__ in, __half* __restrict__ out, int n4) {
    int idx = blockIdx.x * blockDim.x + threadIdx.x;
    int stride = gridDim.x * blockDim.x;
    for (; idx < n4; idx += stride) {
        float4 v = ((const float4*)in)[idx];
        ((__half2*)out)[idx * 2    ] = __floats2half2_rn(v.x, v.y);
        ((__half2*)out)[idx * 2 + 1] = __floats2half2_rn(v.z, v.w);
    }
}

// ---------------- RMSNorm -> fp16 ----------------
__global__ void rmsnorm_kernel(const float* __restrict__ x,
                               const float* __restrict__ w,
                               __half* __restrict__ o) {
    const size_t base = (size_t)blockIdx.x * D_MODEL;
    float ss = 0.f;
    for (int i = threadIdx.x; i < D_MODEL; i += 256) {
        float v = x[base + i];
        ss += v * v;
    }
    ss = block_reduce_sum(ss);
    float r = rsqrtf(ss * (1.0f / D_MODEL) + 1e-6f);
    for (int i = threadIdx.x; i < D_MODEL; i += 256)
        o[base + i] = __float2half_rn(x[base + i] * r * w[i]);
}

// ---------------- RoPE in-place on fp32 qkv (tf32-rounded for flash) ----------------
__global__ void rope_kernel(float* __restrict__ qkv) {
    const int t   = blockIdx.x;
    const int pos = t & (SEQ - 1);
    const int h   = threadIdx.x >> 5;
    const int i   = threadIdx.x & 31;
    float invf = expf(-(2.0f * (float)i / (float)DH) * logf(10000.0f));
    float fr = (float)pos * invf;
    float s, c;
    sincosf(fr, &s, &c);
    float* q = qkv + (size_t)t * (3 * TOT) + h * DH;
    float q1 = q[i], q2 = q[i + 32];
    q[i]      = tf32r(q1 * c - q2 * s);
    q[i + 32] = tf32r(q2 * c + q1 * s);
    float* k = q + TOT;
    float k1 = k[i], k2 = k[i + 32];
    k[i]      = tf32r(k1 * c - k2 * s);
    k[i + 32] = tf32r(k2 * c + k1 * s);
}

// ---------------- FP16 mma GEMM, BK=64, 3-stage ----------------
// C[M,N] = A[M,K] @ B[N,K]^T  (A,B fp16; acc fp32). Epilogues:
//   EPI 1: tf32-round fp32 store    EPI 2: fp32 store + X residual
//   EPI 3: fp16 store of silu(X)*acc (fused SwiGLU)   EPI 0: plain fp32 store
#define EPI_PLAIN  0
#define EPI_ROUND  1
#define EPI_RES    2
#define EPI_SWIGLU 3

#define PW 36                                  // 32-bit words per smem row (64 halves + pad)
#define GSTAGE_W (128 * PW)                    // words per matrix per stage
#define GEMM_SMEM (6 * GSTAGE_W * 4)           // 3 stages x (A+B) = 108 KB

template<int EPI>
__global__ void __launch_bounds__(256, 2)
gemm_f16(const __half* __restrict__ A, int lda,
         const __half* __restrict__ B, int ldb,
         void* __restrict__ Cv, int ldc,
         const float* __restrict__ X, int K) {
    extern __shared__ uint32_t smw[];
    uint32_t* As = smw;                    // [3][GSTAGE_W]
    uint32_t* Bs = smw + 3 * GSTAGE_W;

    const int tid  = threadIdx.x;
    const int lane = tid & 31;
    const int wid  = tid >> 5;
    const int wm_base = (wid >> 2) * 64;       // 2 M-warps x 4 N-warps
    const int wn_base = (wid & 3) * 32;
    const int m0 = blockIdx.y * 128, n0 = blockIdx.x * 128;
    const int lr = lane >> 2, lc = lane & 3;

    float acc[4][4][4];
    #pragma unroll
    for (int i = 0; i < 4; i++)
        #pragma unroll
        for (int j = 0; j < 4; j++)
            #pragma unroll
            for (int r = 0; r < 4; r++) acc[i][j][r] = 0.f;

    const int nt = K / 64;

    auto load_tile = [&](int stg, int kt) {    // kt in halves
        uint32_t as_u = (uint32_t)__cvta_generic_to_shared(As + stg * GSTAGE_W);
        uint32_t bs_u = (uint32_t)__cvta_generic_to_shared(Bs + stg * GSTAGE_W);
        #pragma unroll
        for (int i = 0; i < 4; i++) {          // 128 rows x 8 16B-chunks / 256 thr
            int c = tid + i * 256, row = c >> 3, sub = c & 7;
            uint32_t so = (uint32_t)(row * PW + sub * 4) * 4;   // bytes
            cp16(as_u + so, A + (size_t)(m0 + row) * lda + kt + sub * 8);
            cp16(bs_u + so, B + (size_t)(n0 + row) * ldb + kt + sub * 8);
        }
        asm volatile("cp.async.commit_group;");
    };

    load_tile(0, 0);
    if (nt > 1) load_tile(1, 64);

    for (int t = 0; t < nt; t++) {
        if (t + 1 < nt) asm volatile("cp.async.wait_group 1;");
        else            asm volatile("cp.async.wait_group 0;");
        __syncthreads();
        // stage (t+2)%3 was last read in compute t-1 -> safe to overwrite.
        if (t + 2 < nt) load_tile((t + 2) % 3, (t + 2) * 64);

        const uint32_t* as = As + (t % 3) * GSTAGE_W;
        const uint32_t* bs = Bs + (t % 3) * GSTAGE_W;
        #pragma unroll
        for (int ks = 0; ks < 4; ks++) {       // 4 x k16 steps
            const int kw = ks * 8;             // word offset
            uint32_t af[4][4];
            uint32_t bf[4][2];
            #pragma unroll
            for (int mi = 0; mi < 4; mi++) {
                int mr = wm_base + mi * 16 + lr;
                af[mi][0] = as[(mr    ) * PW + kw + lc    ];
                af[mi][1] = as[(mr + 8) * PW + kw + lc    ];
                af[mi][2] = as[(mr    ) * PW + kw + lc + 4];
                af[mi][3] = as[(mr + 8) * PW + kw + lc + 4];
            }
            #pragma unroll
            for (int nj = 0; nj < 4; nj++) {
                int nr = wn_base + nj * 8 + lr;
                bf[nj][0] = bs[nr * PW + kw + lc    ];
                bf[nj][1] = bs[nr * PW + kw + lc + 4];
            }
            #pragma unroll
            for (int mi = 0; mi < 4; mi++)
                #pragma unroll
                for (int nj = 0; nj < 4; nj++)
                    mma_f16(acc[mi][nj][0], acc[mi][nj][1], acc[mi][nj][2], acc[mi][nj][3],
                            af[mi][0], af[mi][1], af[mi][2], af[mi][3],
                            bf[nj][0], bf[nj][1]);
        }
        __syncthreads();
    }

    #pragma unroll
    for (int mi = 0; mi < 4; mi++) {
        int gm = m0 + wm_base + mi * 16 + lr;
        #pragma unroll
        for (int nj = 0; nj < 4; nj++) {
            int gn = n0 + wn_base + nj * 8 + 2 * lc;
            float2 v0 = make_float2(acc[mi][nj][0], acc[mi][nj][1]);
            float2 v1 = make_float2(acc[mi][nj][2], acc[mi][nj][3]);
            if (EPI == EPI_RES) {
                float2 r0 = *(const float2*)(X + (size_t)gm * ldc + gn);
                float2 r1 = *(const float2*)(X + (size_t)(gm + 8) * ldc + gn);
                v0.x += r0.x; v0.y += r0.y;
                v1.x += r1.x; v1.y += r1.y;
            }
            if (EPI == EPI_SWIGLU) {
                float2 g0 = *(const float2*)(X + (size_t)gm * ldc + gn);
                float2 g1 = *(const float2*)(X + (size_t)(gm + 8) * ldc + gn);
                __half* Ch = (__half*)Cv;
                *(__half2*)(Ch + (size_t)gm * ldc + gn) =
                    __floats2half2_rn(g0.x / (1.f + __expf(-g0.x)) * v0.x,
                                      g0.y / (1.f + __expf(-g0.y)) * v0.y);
                *(__half2*)(Ch + (size_t)(gm + 8) * ldc + gn) =
                    __floats2half2_rn(g1.x / (1.f + __expf(-g1.x)) * v1.x,
                                      g1.y / (1.f + __expf(-g1.y)) * v1.y);
            } else {
                if (EPI == EPI_ROUND) {
                    v0.x = tf32r(v0.x); v0.y = tf32r(v0.y);
                    v1.x = tf32r(v1.x); v1.y = tf32r(v1.y);
                }
                float* C = (float*)Cv;
                *(float2*)(C + (size_t)gm * ldc + gn) = v0;
                *(float2*)(C + (size_t)(gm + 8) * ldc + gn) = v1;
            }
        }
    }
}

// ---------------- Flash attention (R5 core; fp16 output stores) ----------------
#define KPITCH 68
#define VPITCH 72
#define KTILE  (64 * KPITCH)
#define VTILE  (64 * VPITCH)
#define FLASH_SMEM ((2 * KTILE + 2 * VTILE) * 4)

__global__ void __launch_bounds__(256, 1)
flash_kernel(const float* __restrict__ qkv, __half* __restrict__ attn) {
    extern __shared__ float sm[];
    float* Ks = sm;
    float* Vs = sm + 2 * KTILE;

    const int by = blockIdx.x;
    const int z  = blockIdx.y;
    const int b = z >> 4, h = z & 15;
    const int tid = threadIdx.x, lane = tid & 31, w = tid >> 5;
    const int lr = lane >> 2, lc = lane & 3;

    const float* Qb = qkv + (size_t)b * SEQ * 3 * TOT + h * DH;
    const float* Kb = Qb + TOT;
    const float* Vb = Qb + 2 * TOT;
    const int q0 = by * 128 + w * 16;

    const float sc = 0.18033688011f;   // 0.125 * log2(e)
    uint32_t qf[8][4];
    {
        const float* r0 = Qb + (size_t)(q0 + lr) * 3072;
        const float* r1 = Qb + (size_t)(q0 + lr + 8) * 3072;
        #pragma unroll
        for (int ks = 0; ks < 8; ks++) {
            qf[ks][0] = f2tf32(r0[ks * 8 + lc    ] * sc);
            qf[ks][1] = f2tf32(r1[ks * 8 + lc    ] * sc);
            qf[ks][2] = f2tf32(r0[ks * 8 + lc + 4] * sc);
            qf[ks][3] = f2tf32(r1[ks * 8 + lc + 4] * sc);
        }
    }

    float m0 = -1e30f, m8 = -1e30f, l0 = 0.f, l8 = 0.f;
    float o[8][4];
    #pragma unroll
    for (int nd = 0; nd < 8; nd++)
        #pragma unroll
        for (int r = 0; r < 4; r++) o[nd][r] = 0.f;

    const int nt = 2 * by + 2;

    auto load_kv = [&](int t) {
        int buf = t & 1;
        uint32_t ku = (uint32_t)__cvta_generic_to_shared(Ks + buf * KTILE);
        uint32_t vu = (uint32_t)__cvta_generic_to_shared(Vs + buf * VTILE);
        int kv0 = t * 64;
        #pragma unroll
        for (int c = tid; c < 1024; c += 256) {
            int r = c >> 4, cc = c & 15;
            cp16(ku + (uint32_t)(r * KPITCH + cc * 4) * 4,
                 Kb + (size_t)(kv0 + r) * 3072 + cc * 4);
            cp16(vu + (uint32_t)(r * VPITCH + cc * 4) * 4,
                 Vb + (size_t)(kv0 + r) * 3072 + cc * 4);
        }
        asm volatile("cp.async.commit_group;");
    };

    load_kv(0);

    for (int t = 0; t < nt; t++) {
        asm volatile("cp.async.wait_group 0;");
        __syncthreads();
        if (t + 1 < nt) load_kv(t + 1);

        const float* ksm = Ks + (t & 1) * KTILE;
        const float* vsm = Vs + (t & 1) * VTILE;

        float s[8][4];
        #pragma unroll
        for (int nj = 0; nj < 8; nj++) {
            float s0 = 0.f, s1 = 0.f, s2 = 0.f, s3 = 0.f;
            #pragma unroll
            for (int ks = 0; ks < 8; ks++) {
                uint32_t b0 = __float_as_uint(ksm[(nj * 8 + lr) * KPITCH + ks * 8 + lc    ]);
                uint32_t b1 = __float_as_uint(ksm[(nj * 8 + lr) * KPITCH + ks * 8 + lc + 4]);
                mma_tf32(s0, s1, s2, s3,
                         qf[ks][0], qf[ks][1], qf[ks][2], qf[ks][3], b0, b1);
            }
            s[nj][0] = s0; s[nj][1] = s1; s[nj][2] = s2; s[nj][3] = s3;
        }

        if (t >= 2 * by) {
            const int i0 = q0 + lr, i8 = i0 + 8;
            const int cb = t * 64;
            #pragma unroll
            for (int nj = 0; nj < 8; nj++) {
                int j0 = cb + nj * 8 + 2 * lc;
                if (j0     > i0) s[nj][0] = -1e30f;
                if (j0 + 1 > i0) s[nj][1] = -1e30f;
                if (j0     > i8) s[nj][2] = -1e30f;
                if (j0 + 1 > i8) s[nj][3] = -1e30f;
            }
        }

        float mx0 = -1e30f, mx8 = -1e30f;
        #pragma unroll
        for (int nj = 0; nj < 8; nj++) {
            mx0 = fmaxf(mx0, fmaxf(s[nj][0], s[nj][1]));
            mx8 = fmaxf(mx8, fmaxf(s[nj][2], s[nj][3]));
        }
        mx0 = fmaxf(mx0, __shfl_xor_sync(0xffffffffu, mx0, 1));
        mx0 = fmaxf(mx0, __shfl_xor_sync(0xffffffffu, mx0, 2));
        mx8 = fmaxf(mx8, __shfl_xor_sync(0xffffffffu, mx8, 1));
        mx8 = fmaxf(mx8, __shfl_xor_sync(0xffffffffu, mx8, 2));

        float mn0 = fmaxf(m0, mx0), mn8 = fmaxf(m8, mx8);
        float es0 = ex2(m0 - mn0), es8 = ex2(m8 - mn8);
        m0 = mn0; m8 = mn8;

        float sum0 = 0.f, sum8 = 0.f;
        #pragma unroll
        for (int nj = 0; nj < 8; nj++) {
            s[nj][0] = ex2(s[nj][0] - mn0);
            s[nj][1] = ex2(s[nj][1] - mn0);
            s[nj][2] = ex2(s[nj][2] - mn8);
            s[nj][3] = ex2(s[nj][3] - mn8);
            sum0 += s[nj][0] + s[nj][1];
            sum8 += s[nj][2] + s[nj][3];
        }
        sum0 += __shfl_xor_sync(0xffffffffu, sum0, 1);
        sum0 += __shfl_xor_sync(0xffffffffu, sum0, 2);
        sum8 += __shfl_xor_sync(0xffffffffu, sum8, 1);
        sum8 += __shfl_xor_sync(0xffffffffu, sum8, 2);
        l0 = l0 * es0 + sum0;
        l8 = l8 * es8 + sum8;

        #pragma unroll
        for (int nd = 0; nd < 8; nd++) {
            o[nd][0] *= es0; o[nd][1] *= es0;
            o[nd][2] *= es8; o[nd][3] *= es8;
        }

        const int qb = lane & ~3;
        const int sA = qb | (lc >> 1);
        const int sB = qb | ((lc >> 1) + 2);
        const bool odd = lc & 1;
        #pragma unroll
        for (int kc = 0; kc < 8; kc++) {
            float e00 = __shfl_sync(0xffffffffu, s[kc][0], sA);
            float e10 = __shfl_sync(0xffffffffu, s[kc][1], sA);
            float e01 = __shfl_sync(0xffffffffu, s[kc][0], sB);
            float e11 = __shfl_sync(0xffffffffu, s[kc][1], sB);
            float e20 = __shfl_sync(0xffffffffu, s[kc][2], sA);
            float e30 = __shfl_sync(0xffffffffu, s[kc][3], sA);
            float e21 = __shfl_sync(0xffffffffu, s[kc][2], sB);
            float e31 = __shfl_sync(0xffffffffu, s[kc][3], sB);
            uint32_t a0 = f2tf32(odd ? e10 : e00);
            uint32_t a2 = f2tf32(odd ? e11 : e01);
            uint32_t a1 = f2tf32(odd ? e30 : e20);
            uint32_t a3 = f2tf32(odd ? e31 : e21);
            #pragma unroll
            for (int nd = 0; nd < 8; nd++) {
                uint32_t b0 = __float_as_uint(vsm[(kc * 8 + lc    ) * VPITCH + nd * 8 + lr]);
                uint32_t b1 = __float_as_uint(vsm[(kc * 8 + lc + 4) * VPITCH + nd * 8 + lr]);
                mma_tf32(o[nd][0], o[nd][1], o[nd][2], o[nd][3], a0, a1, a2, a3, b0, b1);
            }
        }
        __syncthreads();
    }

    const float inv0 = 1.f / l0, inv8 = 1.f / l8;
    const size_t trow = (size_t)b * SEQ + q0;
    __half* ob0 = attn + (trow + lr    ) * TOT + h * DH;
    __half* ob8 = attn + (trow + lr + 8) * TOT + h * DH;
    #pragma unroll
    for (int nd = 0; nd < 8; nd++) {
        int col = nd * 8 + 2 * lc;
        *(__half2*)(ob0 + col) = __floats2half2_rn(o[nd][0] * inv0, o[nd][1] * inv0);
        *(__half2*)(ob8 + col) = __floats2half2_rn(o[nd][2] * inv8, o[nd][3] * inv8);
    }
}

// ---------------- launch ----------------
extern "C" void kernel_launch(void* const* d_in, const int* in_sizes, int n_in,
                              void* d_out, int out_size) {
    const float* x      = (const float*)d_in[0];
    const float* w_ln1  = (const float*)d_in[1];
    const float* w_qkv  = (const float*)d_in[2];
    const float* w_out  = (const float*)d_in[3];
    const float* w_ln2  = (const float*)d_in[4];
    const float* w_gate = (const float*)d_in[5];
    const float* w_up   = (const float*)d_in[6];
    const float* w_down = (const float*)d_in[7];
    float* out = (float*)d_out;

    void* p;
    cudaGetSymbolAddress(&p, g_hh);    __half* h    = (__half*)p;
    cudaGetSymbolAddress(&p, g_qkv);   float*  qkv  = (float*)p;
    cudaGetSymbolAddress(&p, g_attnh); __half* attn = (__half*)p;
    cudaGetSymbolAddress(&p, g_x2);    float*  x2   = (float*)p;
    cudaGetSymbolAddress(&p, g_gate);  float*  gate = (float*)p;
    cudaGetSymbolAddress(&p, g_ffh);   __half* ffh  = (__half*)p;
    cudaGetSymbolAddress(&p, g_wh);    __half* wh   = (__half*)p;

    __half* wqkv_h  = wh;                      // 3M halves
    __half* wout_h  = wqkv_h + 3*1024*1024;    // 1M
    __half* wgate_h = wout_h + 1024*1024;      // 4M
    __half* wup_h   = wgate_h + 4*1024*1024;   // 4M
    __half* wdown_h = wup_h + 4*1024*1024;     // 4M

    cudaFuncSetAttribute(gemm_f16<EPI_PLAIN>,  cudaFuncAttributeMaxDynamicSharedMemorySize, GEMM_SMEM);
    cudaFuncSetAttribute(gemm_f16<EPI_ROUND>,  cudaFuncAttributeMaxDynamicSharedMemorySize, GEMM_SMEM);
    cudaFuncSetAttribute(gemm_f16<EPI_RES>,    cudaFuncAttributeMaxDynamicSharedMemorySize, GEMM_SMEM);
    cudaFuncSetAttribute(gemm_f16<EPI_SWIGLU>, cudaFuncAttributeMaxDynamicSharedMemorySize, GEMM_SMEM);
    cudaFuncSetAttribute(flash_kernel, cudaFuncAttributeMaxDynamicSharedMemorySize, FLASH_SMEM);

    // 0) convert weights to fp16
    to_half_kernel<<<512, 256>>>(w_qkv,  wqkv_h,  3*1024*1024/4);
    to_half_kernel<<<512, 256>>>(w_out,  wout_h,  1024*1024/4);
    to_half_kernel<<<512, 256>>>(w_gate, wgate_h, 4*1024*1024/4);
    to_half_kernel<<<512, 256>>>(w_up,   wup_h,   4*1024*1024/4);
    to_half_kernel<<<512, 256>>>(w_down, wdown_h, 4*1024*1024/4);

    // 1) h = rmsnorm(x, w_ln1) -> fp16
    rmsnorm_kernel<<<NTOK, 256>>>(x, w_ln1, h);

    // 2) qkv = h @ w_qkv^T -> fp32, tf32-rounded (flash reads raw bits)
    gemm_f16<EPI_ROUND><<<dim3(3*TOT/128, NTOK/128), 256, GEMM_SMEM>>>(
        h, D_MODEL, wqkv_h, D_MODEL, qkv, 3*TOT, nullptr, D_MODEL);

    // 3) RoPE [tf32-rounded]
    rope_kernel<<<NTOK, 512>>>(qkv);

    // 4) flash attention -> attn (fp16)
    flash_kernel<<<dim3(SEQ/128, BATCH*NH), 256, FLASH_SMEM>>>(qkv, attn);

    // 5) x2 = x + attn @ w_out^T
    gemm_f16<EPI_RES><<<dim3(D_MODEL/128, NTOK/128), 256, GEMM_SMEM>>>(
        attn, TOT, wout_h, TOT, x2, D_MODEL, x, TOT);

    // 6) h = rmsnorm(x2, w_ln2) -> fp16
    rmsnorm_kernel<<<NTOK, 256>>>(x2, w_ln2, h);

    // 7) gate = h @ w_gate^T (fp32 raw); then up-proj with fused SwiGLU:
    //    ffh <- fp16(silu(gate) * (h @ w_up^T))
    gemm_f16<EPI_PLAIN><<<dim3(D_FF/128, NTOK/128), 256, GEMM_SMEM>>>(
        h, D_MODEL, wgate_h, D_MODEL, gate, D_FF, nullptr, D_MODEL);
    gemm_f16<EPI_SWIGLU><<<dim3(D_FF/128, NTOK/128), 256, GEMM_SMEM>>>(
        h, D_MODEL, wup_h, D_MODEL, ffh, D_FF, gate, D_MODEL);

    // 8) out = x2 + ffh @ w_down^T
    gemm_f16<EPI_RES><<<dim3(D_MODEL/128, NTOK/128), 256, GEMM_SMEM>>>(
        ffh, D_FF, wdown_h, D_FF, out, D_MODEL, x2, D_FF);
}

// round 11
// speedup vs baseline: 7.3515x; 1.1011x over previous
#include <cuda_runtime.h>
#include <cuda_fp16.h>
#include <math.h>
#include <stdint.h>

// ---------------- problem constants ----------------
#define D_MODEL 1024
#define D_FF    4096
#define NH      16
#define DH      64
#define TOT     1024
#define BATCH   2
#define SEQ     2048
#define NTOK    (BATCH*SEQ)

// ---------------- scratch ----------------
__device__ __half g_hh  [(size_t)NTOK * D_MODEL];        // rmsnorm out (fp16)
__device__ __half g_qkvh[(size_t)NTOK * 3 * TOT];        // qkv (fp16)
__device__ __half g_attnh[(size_t)NTOK * TOT];           // flash out (fp16)
__device__ float  g_x2  [(size_t)NTOK * D_MODEL];        // residual 2 (fp32)
__device__ float  g_gate[(size_t)NTOK * D_FF];           // gate raw (fp32)
__device__ __half g_ffh [(size_t)NTOK * D_FF];           // swiglu out (fp16)
__device__ __half g_wh  [(size_t)16 * 1024 * 1024];      // fp16 weights

// ---------------- helpers ----------------
__device__ __forceinline__ void cp16(uint32_t dst, const void* src) {
    asm volatile("cp.async.cg.shared.global [%0], [%1], 16;" :: "r"(dst), "l"(src));
}
__device__ __forceinline__ float ex2(float x) {
    float r;
    asm("ex2.approx.ftz.f32 %0, %1;" : "=f"(r) : "f"(x));
    return r;
}
__device__ __forceinline__ uint32_t packh2(float lo, float hi) {
    __half2 h = __floats2half2_rn(lo, hi);
    return *reinterpret_cast<uint32_t*>(&h);
}
__device__ __forceinline__ uint32_t scaleh2(uint32_t w, float sc) {
    __half2 h = *reinterpret_cast<__half2*>(&w);
    float2 f = __half22float2(h);
    return packh2(f.x * sc, f.y * sc);
}
__device__ __forceinline__ void mma_f16(float& c0, float& c1, float& c2, float& c3,
                                        uint32_t a0, uint32_t a1, uint32_t a2, uint32_t a3,
                                        uint32_t b0, uint32_t b1) {
    asm volatile(
        "mma.sync.aligned.m16n8k16.row.col.f32.f16.f16.f32 "
        "{%0,%1,%2,%3}, {%4,%5,%6,%7}, {%8,%9}, {%0,%1,%2,%3};"
        : "+f"(c0), "+f"(c1), "+f"(c2), "+f"(c3)
        : "r"(a0), "r"(a1), "r"(a2), "r"(a3), "r"(b0), "r"(b1));
}

// ---------------- block reduction ----------------
__device__ __forceinline__ float block_reduce_sum(float v) {
    __shared__ float sh[33];
    int lane = threadIdx.x & 31, wid = threadIdx.x >> 5;
    #pragma unroll
    for (int o = 16; o; o >>= 1) v += __shfl_xor_sync(0xffffffffu, v, o);
    if (lane == 0) sh[wid] = v;
    __syncthreads();
    if (wid == 0) {
        v = (lane < (blockDim.x >> 5)) ? sh[lane] : 0.f;
        #pragma unroll
        for (int o = 16; o; o >>= 1) v += __shfl_xor_sync(0xffffffffu, v, o);
        if (lane == 0) sh[32] = v;
    }
    __syncthreads();
    float r = sh[32];
    __syncthreads();
    return r;
}

// ---------------- weights fp32 -> fp16 ----------------
__global__ void to_half_kernel(const float* __restrict__ in, __half* __restrict__ out, int n4) {
    int idx = blockIdx.x * blockDim.x + threadIdx.x;
    int stride = gridDim.x * blockDim.x;
    for (; idx < n4; idx += stride) {
        float4 v = ((const float4*)in)[idx];
        ((__half2*)out)[idx * 2    ] = __floats2half2_rn(v.x, v.y);
        ((__half2*)out)[idx * 2 + 1] = __floats2half2_rn(v.z, v.w);
    }
}

// ---------------- RMSNorm -> fp16 ----------------
__global__ void rmsnorm_kernel(const float* __restrict__ x,
                               const float* __restrict__ w,
                               __half* __restrict__ o) {
    const size_t base = (size_t)blockIdx.x * D_MODEL;
    float ss = 0.f;
    for (int i = threadIdx.x; i < D_MODEL; i += 256) {
        float v = x[base + i];
        ss += v * v;
    }
    ss = block_reduce_sum(ss);
    float r = rsqrtf(ss * (1.0f / D_MODEL) + 1e-6f);
    for (int i = threadIdx.x; i < D_MODEL; i += 256)
        o[base + i] = __float2half_rn(x[base + i] * r * w[i]);
}

// ---------------- RoPE in-place on fp16 qkv ----------------
__global__ void rope_kernel(__half* __restrict__ qkv) {
    const int t   = blockIdx.x;
    const int pos = t & (SEQ - 1);
    const int h   = threadIdx.x >> 5;
    const int i   = threadIdx.x & 31;
    float invf = expf(-(2.0f * (float)i / (float)DH) * logf(10000.0f));
    float fr = (float)pos * invf;
    float s, c;
    sincosf(fr, &s, &c);
    __half* q = qkv + (size_t)t * (3 * TOT) + h * DH;
    float q1 = __half2float(q[i]), q2 = __half2float(q[i + 32]);
    q[i]      = __float2half_rn(q1 * c - q2 * s);
    q[i + 32] = __float2half_rn(q2 * c + q1 * s);
    __half* k = q + TOT;
    float k1 = __half2float(k[i]), k2 = __half2float(k[i + 32]);
    k[i]      = __float2half_rn(k1 * c - k2 * s);
    k[i + 32] = __float2half_rn(k2 * c + k1 * s);
}

// ---------------- FP16 mma GEMM, BK=64, 3-stage ----------------
// C[M,N] = A[M,K] @ B[N,K]^T  (A,B fp16; acc fp32). Epilogues:
//   EPI 0: fp32 plain  EPI 1: fp16 store  EPI 2: fp32 + X residual
//   EPI 3: fp16 store of silu(X)*acc (fused SwiGLU)
#define EPI_PLAIN  0
#define EPI_HALF   1
#define EPI_RES    2
#define EPI_SWIGLU 3

#define PW 36                                  // 32-bit words per smem row (64 halves + pad)
#define GSTAGE_W (128 * PW)
#define GEMM_SMEM (6 * GSTAGE_W * 4)           // 108 KB

template<int EPI>
__global__ void __launch_bounds__(256, 2)
gemm_f16(const __half* __restrict__ A, int lda,
         const __half* __restrict__ B, int ldb,
         void* __restrict__ Cv, int ldc,
         const float* __restrict__ X, int K) {
    extern __shared__ uint32_t smw[];
    uint32_t* As = smw;
    uint32_t* Bs = smw + 3 * GSTAGE_W;

    const int tid  = threadIdx.x;
    const int lane = tid & 31;
    const int wid  = tid >> 5;
    const int wm_base = (wid >> 2) * 64;
    const int wn_base = (wid & 3) * 32;
    const int m0 = blockIdx.y * 128, n0 = blockIdx.x * 128;
    const int lr = lane >> 2, lc = lane & 3;

    float acc[4][4][4];
    #pragma unroll
    for (int i = 0; i < 4; i++)
        #pragma unroll
        for (int j = 0; j < 4; j++)
            #pragma unroll
            for (int r = 0; r < 4; r++) acc[i][j][r] = 0.f;

    const int nt = K / 64;

    auto load_tile = [&](int stg, int kt) {
        uint32_t as_u = (uint32_t)__cvta_generic_to_shared(As + stg * GSTAGE_W);
        uint32_t bs_u = (uint32_t)__cvta_generic_to_shared(Bs + stg * GSTAGE_W);
        #pragma unroll
        for (int i = 0; i < 4; i++) {
            int c = tid + i * 256, row = c >> 3, sub = c & 7;
            uint32_t so = (uint32_t)(row * PW + sub * 4) * 4;
            cp16(as_u + so, A + (size_t)(m0 + row) * lda + kt + sub * 8);
            cp16(bs_u + so, B + (size_t)(n0 + row) * ldb + kt + sub * 8);
        }
        asm volatile("cp.async.commit_group;");
    };

    load_tile(0, 0);
    if (nt > 1) load_tile(1, 64);

    for (int t = 0; t < nt; t++) {
        if (t + 1 < nt) asm volatile("cp.async.wait_group 1;");
        else            asm volatile("cp.async.wait_group 0;");
        __syncthreads();
        if (t + 2 < nt) load_tile((t + 2) % 3, (t + 2) * 64);

        const uint32_t* as = As + (t % 3) * GSTAGE_W;
        const uint32_t* bs = Bs + (t % 3) * GSTAGE_W;
        #pragma unroll
        for (int ks = 0; ks < 4; ks++) {
            const int kw = ks * 8;
            uint32_t af[4][4];
            uint32_t bf[4][2];
            #pragma unroll
            for (int mi = 0; mi < 4; mi++) {
                int mr = wm_base + mi * 16 + lr;
                af[mi][0] = as[(mr    ) * PW + kw + lc    ];
                af[mi][1] = as[(mr + 8) * PW + kw + lc    ];
                af[mi][2] = as[(mr    ) * PW + kw + lc + 4];
                af[mi][3] = as[(mr + 8) * PW + kw + lc + 4];
            }
            #pragma unroll
            for (int nj = 0; nj < 4; nj++) {
                int nr = wn_base + nj * 8 + lr;
                bf[nj][0] = bs[nr * PW + kw + lc    ];
                bf[nj][1] = bs[nr * PW + kw + lc + 4];
            }
            #pragma unroll
            for (int mi = 0; mi < 4; mi++)
                #pragma unroll
                for (int nj = 0; nj < 4; nj++)
                    mma_f16(acc[mi][nj][0], acc[mi][nj][1], acc[mi][nj][2], acc[mi][nj][3],
                            af[mi][0], af[mi][1], af[mi][2], af[mi][3],
                            bf[nj][0], bf[nj][1]);
        }
        __syncthreads();
    }

    #pragma unroll
    for (int mi = 0; mi < 4; mi++) {
        int gm = m0 + wm_base + mi * 16 + lr;
        #pragma unroll
        for (int nj = 0; nj < 4; nj++) {
            int gn = n0 + wn_base + nj * 8 + 2 * lc;
            float2 v0 = make_float2(acc[mi][nj][0], acc[mi][nj][1]);
            float2 v1 = make_float2(acc[mi][nj][2], acc[mi][nj][3]);
            if (EPI == EPI_RES) {
                float2 r0 = *(const float2*)(X + (size_t)gm * ldc + gn);
                float2 r1 = *(const float2*)(X + (size_t)(gm + 8) * ldc + gn);
                v0.x += r0.x; v0.y += r0.y;
                v1.x += r1.x; v1.y += r1.y;
                float* C = (float*)Cv;
                *(float2*)(C + (size_t)gm * ldc + gn) = v0;
                *(float2*)(C + (size_t)(gm + 8) * ldc + gn) = v1;
            } else if (EPI == EPI_SWIGLU) {
                float2 g0 = *(const float2*)(X + (size_t)gm * ldc + gn);
                float2 g1 = *(const float2*)(X + (size_t)(gm + 8) * ldc + gn);
                __half* Ch = (__half*)Cv;
                *(__half2*)(Ch + (size_t)gm * ldc + gn) =
                    __floats2half2_rn(g0.x / (1.f + __expf(-g0.x)) * v0.x,
                                      g0.y / (1.f + __expf(-g0.y)) * v0.y);
                *(__half2*)(Ch + (size_t)(gm + 8) * ldc + gn) =
                    __floats2half2_rn(g1.x / (1.f + __expf(-g1.x)) * v1.x,
                                      g1.y / (1.f + __expf(-g1.y)) * v1.y);
            } else if (EPI == EPI_HALF) {
                __half* Ch = (__half*)Cv;
                *(__half2*)(Ch + (size_t)gm * ldc + gn) = __floats2half2_rn(v0.x, v0.y);
                *(__half2*)(Ch + (size_t)(gm + 8) * ldc + gn) = __floats2half2_rn(v1.x, v1.y);
            } else {
                float* C = (float*)Cv;
                *(float2*)(C + (size_t)gm * ldc + gn) = v0;
                *(float2*)(C + (size_t)(gm + 8) * ldc + gn) = v1;
            }
        }
    }
}

// ---------------- FP16 Flash attention ----------------
// grid = (16 q-blocks, 32 bh), 256 thr (8 warps x 16 q-rows), 2 CTAs/SM.
// Q fp16 regs (scaled). K/V fp16 smem double-buffered (pitch 72 halves).
// S = QK^T via m16n8k16. P C-frag pairs == fp16 A-frag pairs -> zero-shuffle PV.
#define FKPW 36                        // words per K/V smem row (72 halves)
#define FTILE_W (64 * FKPW)
#define FLASH_SMEM (4 * FTILE_W * 4)   // K x2 + V x2 = 36 KB

__global__ void __launch_bounds__(256, 2)
flash_kernel(const __half* __restrict__ qkv, __half* __restrict__ attn) {
    extern __shared__ uint32_t smf[];
    uint32_t* Ks = smf;                 // [2][FTILE_W]
    uint32_t* Vs = smf + 2 * FTILE_W;   // [2][FTILE_W]

    const int by = blockIdx.x;
    const int z  = blockIdx.y;
    const int b = z >> 4, h = z & 15;
    const int tid = threadIdx.x, lane = tid & 31, w = tid >> 5;
    const int lr = lane >> 2, lc = lane & 3;

    const __half* Qb = qkv + (size_t)b * SEQ * 3 * TOT + h * DH;
    const __half* Kb = Qb + TOT;
    const __half* Vb = Qb + 2 * TOT;
    const int q0 = by * 128 + w * 16;

    // Q fragments fp16, scaled by 0.125*log2(e)
    const float sc = 0.18033688011f;
    uint32_t qf[4][4];
    {
        const __half* r0 = Qb + (size_t)(q0 + lr) * 3072;
        const __half* r1 = Qb + (size_t)(q0 + lr + 8) * 3072;
        #pragma unroll
        for (int ks = 0; ks < 4; ks++) {
            qf[ks][0] = scaleh2(*(const uint32_t*)(r0 + ks * 16 + 2 * lc    ), sc);
            qf[ks][1] = scaleh2(*(const uint32_t*)(r1 + ks * 16 + 2 * lc    ), sc);
            qf[ks][2] = scaleh2(*(const uint32_t*)(r0 + ks * 16 + 8 + 2 * lc), sc);
            qf[ks][3] = scaleh2(*(const uint32_t*)(r1 + ks * 16 + 8 + 2 * lc), sc);
        }
    }

    float m0 = -1e30f, m8 = -1e30f, l0 = 0.f, l8 = 0.f;
    float o[8][4];
    #pragma unroll
    for (int nd = 0; nd < 8; nd++)
        #pragma unroll
        for (int r = 0; r < 4; r++) o[nd][r] = 0.f;

    const int nt = 2 * by + 2;

    auto load_kv = [&](int t) {
        int buf = t & 1;
        uint32_t ku = (uint32_t)__cvta_generic_to_shared(Ks + buf * FTILE_W);
        uint32_t vu = (uint32_t)__cvta_generic_to_shared(Vs + buf * FTILE_W);
        int kv0 = t * 64;
        // 64 rows x 8 16B-chunks (128B row) each for K and V
        #pragma unroll
        for (int i = 0; i < 2; i++) {
            int c = tid + i * 256, r = c >> 3, cc = c & 7;
            uint32_t so = (uint32_t)(r * FKPW + cc * 4) * 4;
            cp16(ku + so, Kb + (size_t)(kv0 + r) * 3072 + cc * 8);
            cp16(vu + so, Vb + (size_t)(kv0 + r) * 3072 + cc * 8);
        }
        asm volatile("cp.async.commit_group;");
    };

    load_kv(0);

    for (int t = 0; t < nt; t++) {
        asm volatile("cp.async.wait_group 0;");
        __syncthreads();
        if (t + 1 < nt) load_kv(t + 1);

        const uint32_t* ksm = Ks + (t & 1) * FTILE_W;
        const uint32_t* vsm = Vs + (t & 1) * FTILE_W;

        // ---- S = Q @ K^T (16 x 64 per warp), fp16 k16 ----
        float s[8][4];
        #pragma unroll
        for (int nj = 0; nj < 8; nj++) {
            float s0 = 0.f, s1 = 0.f, s2 = 0.f, s3 = 0.f;
            const uint32_t* krow = ksm + (nj * 8 + lr) * FKPW;
            #pragma unroll
            for (int ks = 0; ks < 4; ks++) {
                uint32_t b0 = krow[ks * 8 + lc    ];
                uint32_t b1 = krow[ks * 8 + 4 + lc];
                mma_f16(s0, s1, s2, s3,
                        qf[ks][0], qf[ks][1], qf[ks][2], qf[ks][3], b0, b1);
            }
            s[nj][0] = s0; s[nj][1] = s1; s[nj][2] = s2; s[nj][3] = s3;
        }

        // ---- causal mask (last two tiles only) ----
        if (t >= 2 * by) {
            const int i0 = q0 + lr, i8 = i0 + 8;
            const int cb = t * 64;
            #pragma unroll
            for (int nj = 0; nj < 8; nj++) {
                int j0 = cb + nj * 8 + 2 * lc;
                if (j0     > i0) s[nj][0] = -1e30f;
                if (j0 + 1 > i0) s[nj][1] = -1e30f;
                if (j0     > i8) s[nj][2] = -1e30f;
                if (j0 + 1 > i8) s[nj][3] = -1e30f;
            }
        }

        // ---- online softmax (base 2) ----
        float mx0 = -1e30f, mx8 = -1e30f;
        #pragma unroll
        for (int nj = 0; nj < 8; nj++) {
            mx0 = fmaxf(mx0, fmaxf(s[nj][0], s[nj][1]));
            mx8 = fmaxf(mx8, fmaxf(s[nj][2], s[nj][3]));
        }
        mx0 = fmaxf(mx0, __shfl_xor_sync(0xffffffffu, mx0, 1));
        mx0 = fmaxf(mx0, __shfl_xor_sync(0xffffffffu, mx0, 2));
        mx8 = fmaxf(mx8, __shfl_xor_sync(0xffffffffu, mx8, 1));
        mx8 = fmaxf(mx8, __shfl_xor_sync(0xffffffffu, mx8, 2));

        float mn0 = fmaxf(m0, mx0), mn8 = fmaxf(m8, mx8);
        float es0 = ex2(m0 - mn0), es8 = ex2(m8 - mn8);
        m0 = mn0; m8 = mn8;

        float sum0 = 0.f, sum8 = 0.f;
        #pragma unroll
        for (int nj = 0; nj < 8; nj++) {
            s[nj][0] = ex2(s[nj][0] - mn0);
            s[nj][1] = ex2(s[nj][1] - mn0);
            s[nj][2] = ex2(s[nj][2] - mn8);
            s[nj][3] = ex2(s[nj][3] - mn8);
            sum0 += s[nj][0] + s[nj][1];
            sum8 += s[nj][2] + s[nj][3];
        }
        sum0 += __shfl_xor_sync(0xffffffffu, sum0, 1);
        sum0 += __shfl_xor_sync(0xffffffffu, sum0, 2);
        sum8 += __shfl_xor_sync(0xffffffffu, sum8, 1);
        sum8 += __shfl_xor_sync(0xffffffffu, sum8, 2);
        l0 = l0 * es0 + sum0;
        l8 = l8 * es8 + sum8;

        #pragma unroll
        for (int nd = 0; nd < 8; nd++) {
            o[nd][0] *= es0; o[nd][1] *= es0;
            o[nd][2] *= es8; o[nd][3] *= es8;
        }

        // ---- O += P @ V : fp16 A-frag pairs == own C-frag pairs (no shuffles) ----
        const unsigned short* vh = (const unsigned short*)vsm;
        #pragma unroll
        for (int tt = 0; tt < 4; tt++) {
            uint32_t a0 = packh2(s[2*tt    ][0], s[2*tt    ][1]);
            uint32_t a1 = packh2(s[2*tt    ][2], s[2*tt    ][3]);
            uint32_t a2 = packh2(s[2*tt + 1][0], s[2*tt + 1][1]);
            uint32_t a3 = packh2(s[2*tt + 1][2], s[2*tt + 1][3]);
            const int kbase = 16 * tt + 2 * lc;
            #pragma unroll
            for (int nd = 0; nd < 8; nd++) {
                const int ncol = nd * 8 + lr;
                uint32_t lo0 = vh[(kbase    ) * 72 + ncol];
                uint32_t hi0 = vh[(kbase + 1) * 72 + ncol];
                uint32_t lo1 = vh[(kbase + 8) * 72 + ncol];
                uint32_t hi1 = vh[(kbase + 9) * 72 + ncol];
                mma_f16(o[nd][0], o[nd][1], o[nd][2], o[nd][3],
                        a0, a1, a2, a3, lo0 | (hi0 << 16), lo1 | (hi1 << 16));
            }
        }
        __syncthreads();
    }

    const float inv0 = 1.f / l0, inv8 = 1.f / l8;
    const size_t trow = (size_t)b * SEQ + q0;
    __half* ob0 = attn + (trow + lr    ) * TOT + h * DH;
    __half* ob8 = attn + (trow + lr + 8) * TOT + h * DH;
    #pragma unroll
    for (int nd = 0; nd < 8; nd++) {
        int col = nd * 8 + 2 * lc;
        *(__half2*)(ob0 + col) = __floats2half2_rn(o[nd][0] * inv0, o[nd][1] * inv0);
        *(__half2*)(ob8 + col) = __floats2half2_rn(o[nd][2] * inv8, o[nd][3] * inv8);
    }
}

// ---------------- launch ----------------
extern "C" void kernel_launch(void* const* d_in, const int* in_sizes, int n_in,
                              void* d_out, int out_size) {
    const float* x      = (const float*)d_in[0];
    const float* w_ln1  = (const float*)d_in[1];
    const float* w_qkv  = (const float*)d_in[2];
    const float* w_out  = (const float*)d_in[3];
    const float* w_ln2  = (const float*)d_in[4];
    const float* w_gate = (const float*)d_in[5];
    const float* w_up   = (const float*)d_in[6];
    const float* w_down = (const float*)d_in[7];
    float* out = (float*)d_out;

    void* p;
    cudaGetSymbolAddress(&p, g_hh);    __half* h    = (__half*)p;
    cudaGetSymbolAddress(&p, g_qkvh);  __half* qkv  = (__half*)p;
    cudaGetSymbolAddress(&p, g_attnh); __half* attn = (__half*)p;
    cudaGetSymbolAddress(&p, g_x2);    float*  x2   = (float*)p;
    cudaGetSymbolAddress(&p, g_gate);  float*  gate = (float*)p;
    cudaGetSymbolAddress(&p, g_ffh);   __half* ffh  = (__half*)p;
    cudaGetSymbolAddress(&p, g_wh);    __half* wh   = (__half*)p;

    __half* wqkv_h  = wh;
    __half* wout_h  = wqkv_h + 3*1024*1024;
    __half* wgate_h = wout_h + 1024*1024;
    __half* wup_h   = wgate_h + 4*1024*1024;
    __half* wdown_h = wup_h + 4*1024*1024;

    cudaFuncSetAttribute(gemm_f16<EPI_PLAIN>,  cudaFuncAttributeMaxDynamicSharedMemorySize, GEMM_SMEM);
    cudaFuncSetAttribute(gemm_f16<EPI_HALF>,   cudaFuncAttributeMaxDynamicSharedMemorySize, GEMM_SMEM);
    cudaFuncSetAttribute(gemm_f16<EPI_RES>,    cudaFuncAttributeMaxDynamicSharedMemorySize, GEMM_SMEM);
    cudaFuncSetAttribute(gemm_f16<EPI_SWIGLU>, cudaFuncAttributeMaxDynamicSharedMemorySize, GEMM_SMEM);
    cudaFuncSetAttribute(flash_kernel, cudaFuncAttributeMaxDynamicSharedMemorySize, FLASH_SMEM);

    // 0) convert weights to fp16
    to_half_kernel<<<512, 256>>>(w_qkv,  wqkv_h,  3*1024*1024/4);
    to_half_kernel<<<512, 256>>>(w_out,  wout_h,  1024*1024/4);
    to_half_kernel<<<512, 256>>>(w_gate, wgate_h, 4*1024*1024/4);
    to_half_kernel<<<512, 256>>>(w_up,   wup_h,   4*1024*1024/4);
    to_half_kernel<<<512, 256>>>(w_down, wdown_h, 4*1024*1024/4);

    // 1) h = rmsnorm(x, w_ln1) -> fp16
    rmsnorm_kernel<<<NTOK, 256>>>(x, w_ln1, h);

    // 2) qkv = h @ w_qkv^T -> fp16
    gemm_f16<EPI_HALF><<<dim3(3*TOT/128, NTOK/128), 256, GEMM_SMEM>>>(
        h, D_MODEL, wqkv_h, D_MODEL, qkv, 3*TOT, nullptr, D_MODEL);

    // 3) RoPE (fp16 in-place)
    rope_kernel<<<NTOK, 512>>>(qkv);

    // 4) flash attention -> attn (fp16)
    flash_kernel<<<dim3(SEQ/128, BATCH*NH), 256, FLASH_SMEM>>>(qkv, attn);

    // 5) x2 = x + attn @ w_out^T
    gemm_f16<EPI_RES><<<dim3(D_MODEL/128, NTOK/128), 256, GEMM_SMEM>>>(
        attn, TOT, wout_h, TOT, x2, D_MODEL, x, TOT);

    // 6) h = rmsnorm(x2, w_ln2) -> fp16
    rmsnorm_kernel<<<NTOK, 256>>>(x2, w_ln2, h);

    // 7) gate = h @ w_gate^T (fp32); up-proj fused SwiGLU -> ffh (fp16)
    gemm_f16<EPI_PLAIN><<<dim3(D_FF/128, NTOK/128), 256, GEMM_SMEM>>>(
        h, D_MODEL, wgate_h, D_MODEL, gate, D_FF, nullptr, D_MODEL);
    gemm_f16<EPI_SWIGLU><<<dim3(D_FF/128, NTOK/128), 256, GEMM_SMEM>>>(
        h, D_MODEL, wup_h, D_MODEL, ffh, D_FF, gate, D_MODEL);

    // 8) out = x2 + ffh @ w_down^T
    gemm_f16<EPI_RES><<<dim3(D_MODEL/128, NTOK/128), 256, GEMM_SMEM>>>(
        ffh, D_FF, wdown_h, D_FF, out, D_MODEL, x2, D_FF);
}

// round 12
// speedup vs baseline: 8.1328x; 1.1063x over previous
#include <cuda_runtime.h>
#include <cuda_fp16.h>
#include <math.h>
#include <stdint.h>

// ---------------- problem constants ----------------
#define D_MODEL 1024
#define D_FF    4096
#define NH      16
#define DH      64
#define TOT     1024
#define BATCH   2
#define SEQ     2048
#define NTOK    (BATCH*SEQ)

// ---------------- scratch ----------------
__device__ __half g_hh  [(size_t)NTOK * D_MODEL];
__device__ __half g_qkvh[(size_t)NTOK * 3 * TOT];
__device__ __half g_attnh[(size_t)NTOK * TOT];
__device__ float  g_x2  [(size_t)NTOK * D_MODEL];
__device__ float  g_gate[(size_t)NTOK * D_FF];
__device__ __half g_ffh [(size_t)NTOK * D_FF];
__device__ __half g_wh  [(size_t)16 * 1024 * 1024];

// ---------------- helpers ----------------
__device__ __forceinline__ void cp16(uint32_t dst, const void* src) {
    asm volatile("cp.async.cg.shared.global [%0], [%1], 16;" :: "r"(dst), "l"(src));
}
__device__ __forceinline__ float ex2(float x) {
    float r;
    asm("ex2.approx.ftz.f32 %0, %1;" : "=f"(r) : "f"(x));
    return r;
}
__device__ __forceinline__ uint32_t packh2(float lo, float hi) {
    __half2 h = __floats2half2_rn(lo, hi);
    return *reinterpret_cast<uint32_t*>(&h);
}
__device__ __forceinline__ uint32_t scaleh2(uint32_t w, float sc) {
    __half2 h = *reinterpret_cast<__half2*>(&w);
    float2 f = __half22float2(h);
    return packh2(f.x * sc, f.y * sc);
}
__device__ __forceinline__ void mma_f16(float& c0, float& c1, float& c2, float& c3,
                                        uint32_t a0, uint32_t a1, uint32_t a2, uint32_t a3,
                                        uint32_t b0, uint32_t b1) {
    asm volatile(
        "mma.sync.aligned.m16n8k16.row.col.f32.f16.f16.f32 "
        "{%0,%1,%2,%3}, {%4,%5,%6,%7}, {%8,%9}, {%0,%1,%2,%3};"
        : "+f"(c0), "+f"(c1), "+f"(c2), "+f"(c3)
        : "r"(a0), "r"(a1), "r"(a2), "r"(a3), "r"(b0), "r"(b1));
}
__device__ __forceinline__ void ldsm_x4(uint32_t& r0, uint32_t& r1, uint32_t& r2, uint32_t& r3,
                                        uint32_t addr) {
    asm volatile("ldmatrix.sync.aligned.m8n8.x4.shared.b16 {%0,%1,%2,%3}, [%4];"
                 : "=r"(r0), "=r"(r1), "=r"(r2), "=r"(r3) : "r"(addr));
}
__device__ __forceinline__ void ldsm_x4_t(uint32_t& r0, uint32_t& r1, uint32_t& r2, uint32_t& r3,
                                          uint32_t addr) {
    asm volatile("ldmatrix.sync.aligned.m8n8.x4.trans.shared.b16 {%0,%1,%2,%3}, [%4];"
                 : "=r"(r0), "=r"(r1), "=r"(r2), "=r"(r3) : "r"(addr));
}

// ---------------- block reduction ----------------
__device__ __forceinline__ float block_reduce_sum(float v) {
    __shared__ float sh[33];
    int lane = threadIdx.x & 31, wid = threadIdx.x >> 5;
    #pragma unroll
    for (int o = 16; o; o >>= 1) v += __shfl_xor_sync(0xffffffffu, v, o);
    if (lane == 0) sh[wid] = v;
    __syncthreads();
    if (wid == 0) {
        v = (lane < (blockDim.x >> 5)) ? sh[lane] : 0.f;
        #pragma unroll
        for (int o = 16; o; o >>= 1) v += __shfl_xor_sync(0xffffffffu, v, o);
        if (lane == 0) sh[32] = v;
    }
    __syncthreads();
    float r = sh[32];
    __syncthreads();
    return r;
}

// ---------------- all weights fp32 -> fp16, one launch ----------------
// regions (float4 units): qkv 768K | out 256K | gate 1M | up 1M | down 1M = 4M total
__global__ void to_half_all(const float* __restrict__ wqkv, const float* __restrict__ wout,
                            const float* __restrict__ wgate, const float* __restrict__ wup,
                            const float* __restrict__ wdown, __half* __restrict__ out) {
    int idx = blockIdx.x * blockDim.x + threadIdx.x;
    const int stride = gridDim.x * blockDim.x;
    for (; idx < 4 * 1024 * 1024; idx += stride) {
        const float* src;
        size_t local, ob;
        if (idx < 768 * 1024)            { src = wqkv;  local = idx;                ob = 0; }
        else if (idx < 1024 * 1024)      { src = wout;  local = idx - 768 * 1024;   ob = (size_t)3 * 1024 * 1024; }
        else if (idx < 2 * 1024 * 1024)  { src = wgate; local = idx - 1024 * 1024;  ob = (size_t)4 * 1024 * 1024; }
        else if (idx < 3 * 1024 * 1024)  { src = wup;   local = idx - 2 * 1024 * 1024; ob = (size_t)8 * 1024 * 1024; }
        else                             { src = wdown; local = idx - 3 * 1024 * 1024; ob = (size_t)12 * 1024 * 1024; }
        float4 v = ((const float4*)src)[local];
        __half2* o2 = (__half2*)(out + ob);
        o2[local * 2    ] = __floats2half2_rn(v.x, v.y);
        o2[local * 2 + 1] = __floats2half2_rn(v.z, v.w);
    }
}

// ---------------- RMSNorm -> fp16 ----------------
__global__ void rmsnorm_kernel(const float* __restrict__ x,
                               const float* __restrict__ w,
                               __half* __restrict__ o) {
    const size_t base = (size_t)blockIdx.x * D_MODEL;
    float ss = 0.f;
    for (int i = threadIdx.x; i < D_MODEL; i += 256) {
        float v = x[base + i];
        ss += v * v;
    }
    ss = block_reduce_sum(ss);
    float r = rsqrtf(ss * (1.0f / D_MODEL) + 1e-6f);
    for (int i = threadIdx.x; i < D_MODEL; i += 256)
        o[base + i] = __float2half_rn(x[base + i] * r * w[i]);
}

// ---------------- RoPE in-place on fp16 qkv ----------------
__global__ void rope_kernel(__half* __restrict__ qkv) {
    const int t   = blockIdx.x;
    const int pos = t & (SEQ - 1);
    const int h   = threadIdx.x >> 5;
    const int i   = threadIdx.x & 31;
    float invf = expf(-(2.0f * (float)i / (float)DH) * logf(10000.0f));
    float fr = (float)pos * invf;
    float s, c;
    sincosf(fr, &s, &c);
    __half* q = qkv + (size_t)t * (3 * TOT) + h * DH;
    float q1 = __half2float(q[i]), q2 = __half2float(q[i + 32]);
    q[i]      = __float2half_rn(q1 * c - q2 * s);
    q[i + 32] = __float2half_rn(q2 * c + q1 * s);
    __half* k = q + TOT;
    float k1 = __half2float(k[i]), k2 = __half2float(k[i + 32]);
    k[i]      = __float2half_rn(k1 * c - k2 * s);
    k[i + 32] = __float2half_rn(k2 * c + k1 * s);
}

// ---------------- FP16 mma GEMM, BK=64, 3-stage, ldmatrix mainloop ----------------
#define EPI_PLAIN  0
#define EPI_HALF   1
#define EPI_RES    2
#define EPI_SWIGLU 3

#define PW 36                                  // 32-bit words per smem row
#define GSTAGE_W (128 * PW)
#define GEMM_SMEM (6 * GSTAGE_W * 4)           // 108 KB

template<int EPI>
__global__ void __launch_bounds__(256, 2)
gemm_f16(const __half* __restrict__ A, int lda,
         const __half* __restrict__ B, int ldb,
         void* __restrict__ Cv, int ldc,
         const float* __restrict__ X, int K) {
    extern __shared__ uint32_t smw[];
    uint32_t* As = smw;
    uint32_t* Bs = smw + 3 * GSTAGE_W;

    const int tid  = threadIdx.x;
    const int lane = tid & 31;
    const int wid  = tid >> 5;
    const int wm_base = (wid >> 2) * 64;
    const int wn_base = (wid & 3) * 32;
    const int m0 = blockIdx.y * 128, n0 = blockIdx.x * 128;
    const int lr = lane >> 2, lc = lane & 3;

    // ldmatrix per-lane word offsets
    // A x4: m0=rows0-7@k0, m1=rows8-15@k0, m2=rows0-7@k8, m3=rows8-15@k8
    const int a_off = (lane & 15) * PW + (lane >> 4) * 4;
    // B x4 (2 nj): m0=n0-7@k0, m1=n0-7@k8, m2=n8-15@k0, m3=n8-15@k8
    const int b_off = ((lane & 7) + ((lane >> 4) << 3)) * PW + (((lane >> 3) & 1) * 4);

    float acc[4][4][4];
    #pragma unroll
    for (int i = 0; i < 4; i++)
        #pragma unroll
        for (int j = 0; j < 4; j++)
            #pragma unroll
            for (int r = 0; r < 4; r++) acc[i][j][r] = 0.f;

    const int nt = K / 64;

    auto load_tile = [&](int stg, int kt) {
        uint32_t as_u = (uint32_t)__cvta_generic_to_shared(As + stg * GSTAGE_W);
        uint32_t bs_u = (uint32_t)__cvta_generic_to_shared(Bs + stg * GSTAGE_W);
        #pragma unroll
        for (int i = 0; i < 4; i++) {
            int c = tid + i * 256, row = c >> 3, sub = c & 7;
            uint32_t so = (uint32_t)(row * PW + sub * 4) * 4;
            cp16(as_u + so, A + (size_t)(m0 + row) * lda + kt + sub * 8);
            cp16(bs_u + so, B + (size_t)(n0 + row) * ldb + kt + sub * 8);
        }
        asm volatile("cp.async.commit_group;");
    };

    load_tile(0, 0);
    if (nt > 1) load_tile(1, 64);

    for (int t = 0; t < nt; t++) {
        if (t + 1 < nt) asm volatile("cp.async.wait_group 1;");
        else            asm volatile("cp.async.wait_group 0;");
        __syncthreads();
        if (t + 2 < nt) load_tile((t + 2) % 3, (t + 2) * 64);

        const uint32_t as_u = (uint32_t)__cvta_generic_to_shared(As + (t % 3) * GSTAGE_W);
        const uint32_t bs_u = (uint32_t)__cvta_generic_to_shared(Bs + (t % 3) * GSTAGE_W);
        #pragma unroll
        for (int ks = 0; ks < 4; ks++) {
            const int kw = ks * 8;
            uint32_t af[4][4];
            uint32_t bf[4][2];
            #pragma unroll
            for (int mi = 0; mi < 4; mi++)
                ldsm_x4(af[mi][0], af[mi][1], af[mi][2], af[mi][3],
                        as_u + (uint32_t)((wm_base + mi * 16) * PW + kw + a_off) * 4);
            #pragma unroll
            for (int njp = 0; njp < 2; njp++)
                ldsm_x4(bf[2*njp][0], bf[2*njp][1], bf[2*njp+1][0], bf[2*njp+1][1],
                        bs_u + (uint32_t)((wn_base + njp * 16) * PW + kw + b_off) * 4);
            #pragma unroll
            for (int mi = 0; mi < 4; mi++)
                #pragma unroll
                for (int nj = 0; nj < 4; nj++)
                    mma_f16(acc[mi][nj][0], acc[mi][nj][1], acc[mi][nj][2], acc[mi][nj][3],
                            af[mi][0], af[mi][1], af[mi][2], af[mi][3],
                            bf[nj][0], bf[nj][1]);
        }
        __syncthreads();
    }

    #pragma unroll
    for (int mi = 0; mi < 4; mi++) {
        int gm = m0 + wm_base + mi * 16 + lr;
        #pragma unroll
        for (int nj = 0; nj < 4; nj++) {
            int gn = n0 + wn_base + nj * 8 + 2 * lc;
            float2 v0 = make_float2(acc[mi][nj][0], acc[mi][nj][1]);
            float2 v1 = make_float2(acc[mi][nj][2], acc[mi][nj][3]);
            if (EPI == EPI_RES) {
                float2 r0 = *(const float2*)(X + (size_t)gm * ldc + gn);
                float2 r1 = *(const float2*)(X + (size_t)(gm + 8) * ldc + gn);
                v0.x += r0.x; v0.y += r0.y;
                v1.x += r1.x; v1.y += r1.y;
                float* C = (float*)Cv;
                *(float2*)(C + (size_t)gm * ldc + gn) = v0;
                *(float2*)(C + (size_t)(gm + 8) * ldc + gn) = v1;
            } else if (EPI == EPI_SWIGLU) {
                float2 g0 = *(const float2*)(X + (size_t)gm * ldc + gn);
                float2 g1 = *(const float2*)(X + (size_t)(gm + 8) * ldc + gn);
                __half* Ch = (__half*)Cv;
                *(__half2*)(Ch + (size_t)gm * ldc + gn) =
                    __floats2half2_rn(g0.x / (1.f + __expf(-g0.x)) * v0.x,
                                      g0.y / (1.f + __expf(-g0.y)) * v0.y);
                *(__half2*)(Ch + (size_t)(gm + 8) * ldc + gn) =
                    __floats2half2_rn(g1.x / (1.f + __expf(-g1.x)) * v1.x,
                                      g1.y / (1.f + __expf(-g1.y)) * v1.y);
            } else if (EPI == EPI_HALF) {
                __half* Ch = (__half*)Cv;
                *(__half2*)(Ch + (size_t)gm * ldc + gn) = __floats2half2_rn(v0.x, v0.y);
                *(__half2*)(Ch + (size_t)(gm + 8) * ldc + gn) = __floats2half2_rn(v1.x, v1.y);
            } else {
                float* C = (float*)Cv;
                *(float2*)(C + (size_t)gm * ldc + gn) = v0;
                *(float2*)(C + (size_t)(gm + 8) * ldc + gn) = v1;
            }
        }
    }
}

// ---------------- FP16 Flash attention, ldmatrix loads ----------------
#define FKPW 36                        // words per K/V smem row (72 halves)
#define FTILE_W (64 * FKPW)
#define FLASH_SMEM (4 * FTILE_W * 4)   // 36 KB

__global__ void __launch_bounds__(256, 2)
flash_kernel(const __half* __restrict__ qkv, __half* __restrict__ attn) {
    extern __shared__ uint32_t smf[];
    uint32_t* Ks = smf;
    uint32_t* Vs = smf + 2 * FTILE_W;

    const int by = blockIdx.x;
    const int z  = blockIdx.y;
    const int b = z >> 4, h = z & 15;
    const int tid = threadIdx.x, lane = tid & 31, w = tid >> 5;
    const int lr = lane >> 2, lc = lane & 3;

    const __half* Qb = qkv + (size_t)b * SEQ * 3 * TOT + h * DH;
    const __half* Kb = Qb + TOT;
    const __half* Vb = Qb + 2 * TOT;
    const int q0 = by * 128 + w * 16;

    // K ldmatrix (non-trans, 2 nj per x4): per-lane word offset
    const int kb_off = ((lane & 7) + ((lane >> 4) << 3)) * FKPW + (((lane >> 3) & 1) * 4);
    // V ldmatrix (trans, 2 nd per x4): per-lane half offset
    const int v_off_h = (lane & 15) * 72 + (lane >> 4) * 8;

    // Q fragments fp16, scaled by 0.125*log2(e)
    const float sc = 0.18033688011f;
    uint32_t qf[4][4];
    {
        const __half* r0 = Qb + (size_t)(q0 + lr) * 3072;
        const __half* r1 = Qb + (size_t)(q0 + lr + 8) * 3072;
        #pragma unroll
        for (int ks = 0; ks < 4; ks++) {
            qf[ks][0] = scaleh2(*(const uint32_t*)(r0 + ks * 16 + 2 * lc    ), sc);
            qf[ks][1] = scaleh2(*(const uint32_t*)(r1 + ks * 16 + 2 * lc    ), sc);
            qf[ks][2] = scaleh2(*(const uint32_t*)(r0 + ks * 16 + 8 + 2 * lc), sc);
            qf[ks][3] = scaleh2(*(const uint32_t*)(r1 + ks * 16 + 8 + 2 * lc), sc);
        }
    }

    float m0 = -1e30f, m8 = -1e30f, l0 = 0.f, l8 = 0.f;
    float o[8][4];
    #pragma unroll
    for (int nd = 0; nd < 8; nd++)
        #pragma unroll
        for (int r = 0; r < 4; r++) o[nd][r] = 0.f;

    const int nt = 2 * by + 2;

    auto load_kv = [&](int t) {
        int buf = t & 1;
        uint32_t ku = (uint32_t)__cvta_generic_to_shared(Ks + buf * FTILE_W);
        uint32_t vu = (uint32_t)__cvta_generic_to_shared(Vs + buf * FTILE_W);
        int kv0 = t * 64;
        #pragma unroll
        for (int i = 0; i < 2; i++) {
            int c = tid + i * 256, r = c >> 3, cc = c & 7;
            uint32_t so = (uint32_t)(r * FKPW + cc * 4) * 4;
            cp16(ku + so, Kb + (size_t)(kv0 + r) * 3072 + cc * 8);
            cp16(vu + so, Vb + (size_t)(kv0 + r) * 3072 + cc * 8);
        }
        asm volatile("cp.async.commit_group;");
    };

    load_kv(0);

    for (int t = 0; t < nt; t++) {
        asm volatile("cp.async.wait_group 0;");
        __syncthreads();
        if (t + 1 < nt) load_kv(t + 1);

        const uint32_t ks_u = (uint32_t)__cvta_generic_to_shared(Ks + (t & 1) * FTILE_W);
        const uint32_t vs_u = (uint32_t)__cvta_generic_to_shared(Vs + (t & 1) * FTILE_W);

        // ---- S = Q @ K^T (16 x 64 per warp) ----
        float s[8][4];
        #pragma unroll
        for (int nj = 0; nj < 8; nj++)
            #pragma unroll
            for (int r = 0; r < 4; r++) s[nj][r] = 0.f;
        #pragma unroll
        for (int ks = 0; ks < 4; ks++) {
            const int kw = ks * 8;
            #pragma unroll
            for (int njp = 0; njp < 4; njp++) {
                uint32_t b00, b01, b10, b11;
                ldsm_x4(b00, b01, b10, b11,
                        ks_u + (uint32_t)(njp * 16 * FKPW + kw + kb_off) * 4);
                mma_f16(s[2*njp  ][0], s[2*njp  ][1], s[2*njp  ][2], s[2*njp  ][3],
                        qf[ks][0], qf[ks][1], qf[ks][2], qf[ks][3], b00, b01);
                mma_f16(s[2*njp+1][0], s[2*njp+1][1], s[2*njp+1][2], s[2*njp+1][3],
                        qf[ks][0], qf[ks][1], qf[ks][2], qf[ks][3], b10, b11);
            }
        }

        // ---- causal mask (last two tiles only) ----
        if (t >= 2 * by) {
            const int i0 = q0 + lr, i8 = i0 + 8;
            const int cb = t * 64;
            #pragma unroll
            for (int nj = 0; nj < 8; nj++) {
                int j0 = cb + nj * 8 + 2 * lc;
                if (j0     > i0) s[nj][0] = -1e30f;
                if (j0 + 1 > i0) s[nj][1] = -1e30f;
                if (j0     > i8) s[nj][2] = -1e30f;
                if (j0 + 1 > i8) s[nj][3] = -1e30f;
            }
        }

        // ---- online softmax (base 2) ----
        float mx0 = -1e30f, mx8 = -1e30f;
        #pragma unroll
        for (int nj = 0; nj < 8; nj++) {
            mx0 = fmaxf(mx0, fmaxf(s[nj][0], s[nj][1]));
            mx8 = fmaxf(mx8, fmaxf(s[nj][2], s[nj][3]));
        }
        mx0 = fmaxf(mx0, __shfl_xor_sync(0xffffffffu, mx0, 1));
        mx0 = fmaxf(mx0, __shfl_xor_sync(0xffffffffu, mx0, 2));
        mx8 = fmaxf(mx8, __shfl_xor_sync(0xffffffffu, mx8, 1));
        mx8 = fmaxf(mx8, __shfl_xor_sync(0xffffffffu, mx8, 2));

        float mn0 = fmaxf(m0, mx0), mn8 = fmaxf(m8, mx8);
        float es0 = ex2(m0 - mn0), es8 = ex2(m8 - mn8);
        m0 = mn0; m8 = mn8;

        float sum0 = 0.f, sum8 = 0.f;
        #pragma unroll
        for (int nj = 0; nj < 8; nj++) {
            s[nj][0] = ex2(s[nj][0] - mn0);
            s[nj][1] = ex2(s[nj][1] - mn0);
            s[nj][2] = ex2(s[nj][2] - mn8);
            s[nj][3] = ex2(s[nj][3] - mn8);
            sum0 += s[nj][0] + s[nj][1];
            sum8 += s[nj][2] + s[nj][3];
        }
        sum0 += __shfl_xor_sync(0xffffffffu, sum0, 1);
        sum0 += __shfl_xor_sync(0xffffffffu, sum0, 2);
        sum8 += __shfl_xor_sync(0xffffffffu, sum8, 1);
        sum8 += __shfl_xor_sync(0xffffffffu, sum8, 2);
        l0 = l0 * es0 + sum0;
        l8 = l8 * es8 + sum8;

        #pragma unroll
        for (int nd = 0; nd < 8; nd++) {
            o[nd][0] *= es0; o[nd][1] *= es0;
            o[nd][2] *= es8; o[nd][3] *= es8;
        }

        // ---- O += P @ V : a-frags from own s regs; b-frags via ldmatrix.trans ----
        #pragma unroll
        for (int tt = 0; tt < 4; tt++) {
            uint32_t a0 = packh2(s[2*tt    ][0], s[2*tt    ][1]);
            uint32_t a1 = packh2(s[2*tt    ][2], s[2*tt    ][3]);
            uint32_t a2 = packh2(s[2*tt + 1][0], s[2*tt + 1][1]);
            uint32_t a3 = packh2(s[2*tt + 1][2], s[2*tt + 1][3]);
            #pragma unroll
            for (int ndp = 0; ndp < 4; ndp++) {
                uint32_t b00, b01, b10, b11;
                // m0: V[k0-7][n0-7], m1: V[k8-15][n0-7], m2/m3: next 8 n-cols
                ldsm_x4_t(b00, b01, b10, b11,
                          vs_u + (uint32_t)(tt * 16 * 72 + ndp * 16 + v_off_h) * 2);
                mma_f16(o[2*ndp  ][0], o[2*ndp  ][1], o[2*ndp  ][2], o[2*ndp  ][3],
                        a0, a1, a2, a3, b00, b01);
                mma_f16(o[2*ndp+1][0], o[2*ndp+1][1], o[2*ndp+1][2], o[2*ndp+1][3],
                        a0, a1, a2, a3, b10, b11);
            }
        }
        __syncthreads();
    }

    const float inv0 = 1.f / l0, inv8 = 1.f / l8;
    const size_t trow = (size_t)b * SEQ + q0;
    __half* ob0 = attn + (trow + lr    ) * TOT + h * DH;
    __half* ob8 = attn + (trow + lr + 8) * TOT + h * DH;
    #pragma unroll
    for (int nd = 0; nd < 8; nd++) {
        int col = nd * 8 + 2 * lc;
        *(__half2*)(ob0 + col) = __floats2half2_rn(o[nd][0] * inv0, o[nd][1] * inv0);
        *(__half2*)(ob8 + col) = __floats2half2_rn(o[nd][2] * inv8, o[nd][3] * inv8);
    }
}

// ---------------- launch ----------------
extern "C" void kernel_launch(void* const* d_in, const int* in_sizes, int n_in,
                              void* d_out, int out_size) {
    const float* x      = (const float*)d_in[0];
    const float* w_ln1  = (const float*)d_in[1];
    const float* w_qkv  = (const float*)d_in[2];
    const float* w_out  = (const float*)d_in[3];
    const float* w_ln2  = (const float*)d_in[4];
    const float* w_gate = (const float*)d_in[5];
    const float* w_up   = (const float*)d_in[6];
    const float* w_down = (const float*)d_in[7];
    float* out = (float*)d_out;

    void* p;
    cudaGetSymbolAddress(&p, g_hh);    __half* h    = (__half*)p;
    cudaGetSymbolAddress(&p, g_qkvh);  __half* qkv  = (__half*)p;
    cudaGetSymbolAddress(&p, g_attnh); __half* attn = (__half*)p;
    cudaGetSymbolAddress(&p, g_x2);    float*  x2   = (float*)p;
    cudaGetSymbolAddress(&p, g_gate);  float*  gate = (float*)p;
    cudaGetSymbolAddress(&p, g_ffh);   __half* ffh  = (__half*)p;
    cudaGetSymbolAddress(&p, g_wh);    __half* wh   = (__half*)p;

    __half* wqkv_h  = wh;
    __half* wout_h  = wqkv_h + 3*1024*1024;
    __half* wgate_h = wout_h + 1024*1024;
    __half* wup_h   = wgate_h + 4*1024*1024;
    __half* wdown_h = wup_h + 4*1024*1024;

    cudaFuncSetAttribute(gemm_f16<EPI_PLAIN>,  cudaFuncAttributeMaxDynamicSharedMemorySize, GEMM_SMEM);
    cudaFuncSetAttribute(gemm_f16<EPI_HALF>,   cudaFuncAttributeMaxDynamicSharedMemorySize, GEMM_SMEM);
    cudaFuncSetAttribute(gemm_f16<EPI_RES>,    cudaFuncAttributeMaxDynamicSharedMemorySize, GEMM_SMEM);
    cudaFuncSetAttribute(gemm_f16<EPI_SWIGLU>, cudaFuncAttributeMaxDynamicSharedMemorySize, GEMM_SMEM);
    cudaFuncSetAttribute(flash_kernel, cudaFuncAttributeMaxDynamicSharedMemorySize, FLASH_SMEM);

    // 0) convert all weights to fp16 (single launch)
    to_half_all<<<512, 256>>>(w_qkv, w_out, w_gate, w_up, w_down, wh);

    // 1) h = rmsnorm(x, w_ln1) -> fp16
    rmsnorm_kernel<<<NTOK, 256>>>(x, w_ln1, h);

    // 2) qkv = h @ w_qkv^T -> fp16
    gemm_f16<EPI_HALF><<<dim3(3*TOT/128, NTOK/128), 256, GEMM_SMEM>>>(
        h, D_MODEL, wqkv_h, D_MODEL, qkv, 3*TOT, nullptr, D_MODEL);

    // 3) RoPE (fp16 in-place)
    rope_kernel<<<NTOK, 512>>>(qkv);

    // 4) flash attention -> attn (fp16)
    flash_kernel<<<dim3(SEQ/128, BATCH*NH), 256, FLASH_SMEM>>>(qkv, attn);

    // 5) x2 = x + attn @ w_out^T
    gemm_f16<EPI_RES><<<dim3(D_MODEL/128, NTOK/128), 256, GEMM_SMEM>>>(
        attn, TOT, wout_h, TOT, x2, D_MODEL, x, TOT);

    // 6) h = rmsnorm(x2, w_ln2) -> fp16
    rmsnorm_kernel<<<NTOK, 256>>>(x2, w_ln2, h);

    // 7) gate = h @ w_gate^T (fp32); up-proj fused SwiGLU -> ffh (fp16)
    gemm_f16<EPI_PLAIN><<<dim3(D_FF/128, NTOK/128), 256, GEMM_SMEM>>>(
        h, D_MODEL, wgate_h, D_MODEL, gate, D_FF, nullptr, D_MODEL);
    gemm_f16<EPI_SWIGLU><<<dim3(D_FF/128, NTOK/128), 256, GEMM_SMEM>>>(
        h, D_MODEL, wup_h, D_MODEL, ffh, D_FF, gate, D_MODEL);

    // 8) out = x2 + ffh @ w_down^T
    gemm_f16<EPI_RES><<<dim3(D_MODEL/128, NTOK/128), 256, GEMM_SMEM>>>(
        ffh, D_FF, wdown_h, D_FF, out, D_MODEL, x2, D_FF);
}